// round 15
// baseline (speedup 1.0000x reference)
#include <cuda_runtime.h>
#include <cuda_bf16.h>
#include <cstdint>

// Problem constants (fixed by the dataset)
#define NN 100000
#define EE 500000
#define NF 128
#define ATTR_W 16
#define STATE_W 12
#define REL_W 4
#define PSTEP 2

// Scratch (device globals; no runtime allocation allowed)
__device__ float g_pe [NN * NF];
__device__ float g_ee [EE * NF];
__device__ float g_eff[NN * NF];
__device__ float g_agg[NN * NF];
__device__ float g_attr_r [NN * ATTR_W];   // tf32-pre-rounded inputs
__device__ float g_state_r[NN * STATE_W];
__device__ float g_ra_r   [EE * REL_W];

// ---------------------------------------------------------------------------
// helpers
// ---------------------------------------------------------------------------
__device__ __forceinline__ uint32_t cvt_tf32(float x) {
    uint32_t r;
    asm("cvt.rna.tf32.f32 %0, %1;" : "=r"(r) : "f"(x));
    return r;
}
__device__ __forceinline__ float cvt_tf32f(float x) {
    return __uint_as_float(cvt_tf32(x));
}

__device__ __forceinline__ void mma_tf32(float* c, const uint32_t* a, const uint32_t* b) {
    asm volatile(
        "mma.sync.aligned.m16n8k8.row.col.f32.tf32.tf32.f32 "
        "{%0,%1,%2,%3}, {%4,%5,%6,%7}, {%8,%9}, {%0,%1,%2,%3};"
        : "+f"(c[0]), "+f"(c[1]), "+f"(c[2]), "+f"(c[3])
        : "r"(a[0]), "r"(a[1]), "r"(a[2]), "r"(a[3]), "r"(b[0]), "r"(b[1]));
}

__device__ __forceinline__ void ldsm_x4(uint32_t* r, uint32_t addr) {
    asm volatile("ldmatrix.sync.aligned.m8n8.x4.shared.b16 {%0,%1,%2,%3}, [%4];"
                 : "=r"(r[0]), "=r"(r[1]), "=r"(r[2]), "=r"(r[3]) : "r"(addr));
}
__device__ __forceinline__ void ldsm_x2(uint32_t* r, uint32_t addr) {
    asm volatile("ldmatrix.sync.aligned.m8n8.x2.shared.b16 {%0,%1}, [%2];"
                 : "=r"(r[0]), "=r"(r[1]) : "r"(addr));
}

__device__ __forceinline__ void red2(float* p, float a, float b) {
    asm volatile("red.global.add.v2.f32 [%0], {%1, %2};" :: "l"(p), "f"(a), "f"(b) : "memory");
}

__device__ __forceinline__ uint32_t smem_u32(const void* p) {
    uint32_t a;
    asm("{ .reg .u64 t; cvta.to.shared.u64 t, %1; cvt.u32.u64 %0, t; }" : "=r"(a) : "l"(p));
    return a;
}

// 16-byte async copy, zero-fill when !valid
__device__ __forceinline__ void cp_async16(uint32_t dst, const float* src, bool valid) {
    int sz = valid ? 16 : 0;
    asm volatile("cp.async.ca.shared.global [%0], [%1], 16, %2;"
                 :: "r"(dst), "l"(src), "r"(sz) : "memory");
}
#define CP_COMMIT() asm volatile("cp.async.commit_group;" ::: "memory")
#define CP_WAIT0()  asm volatile("cp.async.wait_group 0;" ::: "memory")

// weight swizzle (k-major, for node_enc): addr = k*128 + (n ^ ((k&3)<<3))
#define WSW(k, n) (((k) << 7) + ((n) ^ (((k) & 3) << 3)))
// transposed weight swizzle, stride S floats: addr = n*S + (k ^ ((n&7)<<2))
#define WTS(nn, k, S) ((nn) * (S) + ((k) ^ (((nn) & 7) << 2)))
// activation swizzle (stride 128): addr = r*128 + (c ^ ((r&7)<<2))
#define ASW(r, c) (((r) << 7) + ((c) ^ (((r) & 7) << 2)))
// chunk swizzle (stride 32): addr = r*32 + (c ^ ((r&7)<<2)), c in 0..31
#define ACSW(r, c) (((r) << 5) + ((c) ^ (((r) & 7) << 2)))

// ---------------------------------------------------------------------------
// zero kernel (float4) and input pre-rounding
// ---------------------------------------------------------------------------
__global__ void k_zero(float4* p, int n4) {
    int i = blockIdx.x * blockDim.x + threadIdx.x;
    int stride = gridDim.x * blockDim.x;
    float4 z = make_float4(0.f, 0.f, 0.f, 0.f);
    for (; i < n4; i += stride) p[i] = z;
}

__global__ void k_round3(const float* __restrict__ a, float* __restrict__ ar, int na,
                         const float* __restrict__ s, float* __restrict__ sr, int ns,
                         const float* __restrict__ r, float* __restrict__ rr, int nr) {
    int i = blockIdx.x * blockDim.x + threadIdx.x;
    int stride = gridDim.x * blockDim.x;
    for (int j = i; j < na; j += stride) ar[j] = cvt_tf32f(a[j]);
    for (int j = i; j < ns; j += stride) sr[j] = cvt_tf32f(s[j]);
    for (int j = i; j < nr; j += stride) rr[j] = cvt_tf32f(r[j]);
}

// ---------------------------------------------------------------------------
// Node encoder via mma.sync tf32 (round-14 passing, unchanged)
// ---------------------------------------------------------------------------
#define NE_OFF_B1   0
#define NE_OFF_B2   512
#define NE_OFF_IN   1024
#define NE_OFF_W1   (NE_OFF_IN + 16384)
#define NE_OFF_W2   (NE_OFF_W1 + 16384)
#define NE_OFF_ACT  (NE_OFF_W2 + 65536)
#define NE_SMEM_BYTES (NE_OFF_ACT + 65536)

__global__ __launch_bounds__(256, 1) void k_node_enc_mma(
    const float* __restrict__ attr, const float* __restrict__ state,
    const float* __restrict__ w1, const float* __restrict__ b1,
    const float* __restrict__ w2, const float* __restrict__ b2,
    float* __restrict__ pe, int n)
{
    extern __shared__ char smem[];
    float*    s_b1 = (float*)   (smem + NE_OFF_B1);
    float*    s_b2 = (float*)   (smem + NE_OFF_B2);
    uint32_t* INs  = (uint32_t*)(smem + NE_OFF_IN);
    uint32_t* W1s  = (uint32_t*)(smem + NE_OFF_W1);
    uint32_t* W2s  = (uint32_t*)(smem + NE_OFF_W2);
    uint32_t* As   = (uint32_t*)(smem + NE_OFF_ACT);

    const int tid = threadIdx.x;
    const int wid = tid >> 5;
    const int lane = tid & 31;
    const int grp = lane >> 2;
    const int tg  = lane & 3;
    const int wm  = wid & 3;
    const int wn  = wid >> 2;

    for (int idx = tid; idx < 32 * 128; idx += 256) {
        int k = idx >> 7, nn = idx & 127;
        float v = (k < 28) ? w1[k * NF + nn] : 0.f;
        W1s[WSW(k, nn)] = cvt_tf32(v);
    }
    for (int idx = tid; idx < 128 * 128; idx += 256) {
        int k = idx >> 7, nn = idx & 127;
        W2s[WSW(k, nn)] = cvt_tf32(w2[k * NF + nn]);
    }
    if (tid < 128) { s_b1[tid] = b1[tid]; s_b2[tid] = b2[tid]; }
    __syncthreads();

    const int ntiles = (n + 127) >> 7;
    const int r_st   = tid >> 1;
    const int half   = tid & 1;

    float acc[2][8][4];

    for (int tile = blockIdx.x; tile < ntiles; tile += gridDim.x) {
        const int n0 = tile << 7;
        const int row = n0 + r_st;
        const bool rv = (row < n);

        if (half == 0) {
#pragma unroll
            for (int q = 0; q < 4; q++) {
                float4 v = rv ? *(const float4*)(attr + (size_t)row * ATTR_W + q * 4)
                              : make_float4(0.f, 0.f, 0.f, 0.f);
                uint4 u = { cvt_tf32(v.x), cvt_tf32(v.y), cvt_tf32(v.z), cvt_tf32(v.w) };
                *(uint4*)(INs + ACSW(r_st, q * 4)) = u;
            }
        } else {
#pragma unroll
            for (int q = 0; q < 3; q++) {
                float4 v = rv ? *(const float4*)(state + (size_t)row * STATE_W + q * 4)
                              : make_float4(0.f, 0.f, 0.f, 0.f);
                uint4 u = { cvt_tf32(v.x), cvt_tf32(v.y), cvt_tf32(v.z), cvt_tf32(v.w) };
                *(uint4*)(INs + ACSW(r_st, 16 + q * 4)) = u;
            }
            uint4 z = { 0u, 0u, 0u, 0u };
            *(uint4*)(INs + ACSW(r_st, 28)) = z;
        }
        __syncthreads();

        // layer 1 (k=32)
#pragma unroll
        for (int mt = 0; mt < 2; mt++)
#pragma unroll
            for (int nt = 0; nt < 8; nt++)
#pragma unroll
                for (int i = 0; i < 4; i++) acc[mt][nt][i] = 0.f;
#pragma unroll
        for (int s = 0; s < 4; s++) {
            const int kk = s * 8;
            uint32_t bf[8][2];
#pragma unroll
            for (int nt = 0; nt < 8; nt++) {
                int n_sw = (wn * 64 + nt * 8 + grp) ^ (tg << 3);
                bf[nt][0] = W1s[((kk + tg) << 7) + n_sw];
                bf[nt][1] = W1s[((kk + tg + 4) << 7) + n_sw];
            }
#pragma unroll
            for (int mt = 0; mt < 2; mt++) {
                int rb = wm * 32 + mt * 16;
                uint32_t af[4];
                af[0] = INs[ACSW(rb + grp,     kk + tg)];
                af[1] = INs[ACSW(rb + grp + 8, kk + tg)];
                af[2] = INs[ACSW(rb + grp,     kk + tg + 4)];
                af[3] = INs[ACSW(rb + grp + 8, kk + tg + 4)];
#pragma unroll
                for (int nt = 0; nt < 8; nt++)
                    mma_tf32(acc[mt][nt], af, bf[nt]);
            }
        }

        // h1 -> As
#pragma unroll
        for (int mt = 0; mt < 2; mt++) {
            int r_lo = wm * 32 + mt * 16 + grp;
            int r_hi = r_lo + 8;
#pragma unroll
            for (int nt = 0; nt < 8; nt++) {
                int col = wn * 64 + nt * 8 + tg * 2;
                float b0 = s_b1[col], b1v = s_b1[col + 1];
                uint2 lo = { cvt_tf32(fmaxf(acc[mt][nt][0] + b0, 0.f)),
                             cvt_tf32(fmaxf(acc[mt][nt][1] + b1v, 0.f)) };
                uint2 hi = { cvt_tf32(fmaxf(acc[mt][nt][2] + b0, 0.f)),
                             cvt_tf32(fmaxf(acc[mt][nt][3] + b1v, 0.f)) };
                *(uint2*)(As + ASW(r_lo, col)) = lo;
                *(uint2*)(As + ASW(r_hi, col)) = hi;
            }
        }
        __syncthreads();

        // layer 2 (k=128)
#pragma unroll
        for (int mt = 0; mt < 2; mt++)
#pragma unroll
            for (int nt = 0; nt < 8; nt++)
#pragma unroll
                for (int i = 0; i < 4; i++) acc[mt][nt][i] = 0.f;
#pragma unroll
        for (int s = 0; s < 16; s++) {
            const int kk = s * 8;
            uint32_t bf[8][2];
#pragma unroll
            for (int nt = 0; nt < 8; nt++) {
                int n_sw = (wn * 64 + nt * 8 + grp) ^ (tg << 3);
                bf[nt][0] = W2s[((kk + tg) << 7) + n_sw];
                bf[nt][1] = W2s[((kk + tg + 4) << 7) + n_sw];
            }
#pragma unroll
            for (int mt = 0; mt < 2; mt++) {
                int rb = wm * 32 + mt * 16;
                uint32_t af[4];
                af[0] = As[ASW(rb + grp,     kk + tg)];
                af[1] = As[ASW(rb + grp + 8, kk + tg)];
                af[2] = As[ASW(rb + grp,     kk + tg + 4)];
                af[3] = As[ASW(rb + grp + 8, kk + tg + 4)];
#pragma unroll
                for (int nt = 0; nt < 8; nt++)
                    mma_tf32(acc[mt][nt], af, bf[nt]);
            }
        }
        __syncthreads();

        // store pe (tf32-rounded)
#pragma unroll
        for (int mt = 0; mt < 2; mt++) {
            int r_lo = wm * 32 + mt * 16 + grp;
            int r_hi = r_lo + 8;
            bool v_lo = (n0 + r_lo) < n;
            bool v_hi = (n0 + r_hi) < n;
#pragma unroll
            for (int nt = 0; nt < 8; nt++) {
                int col = wn * 64 + nt * 8 + tg * 2;
                float b0 = s_b2[col], b1v = s_b2[col + 1];
                if (v_lo) {
                    float2 v = { cvt_tf32f(fmaxf(acc[mt][nt][0] + b0, 0.f)),
                                 cvt_tf32f(fmaxf(acc[mt][nt][1] + b1v, 0.f)) };
                    *(float2*)(pe + (size_t)(n0 + r_lo) * NF + col) = v;
                }
                if (v_hi) {
                    float2 v = { cvt_tf32f(fmaxf(acc[mt][nt][2] + b0, 0.f)),
                                 cvt_tf32f(fmaxf(acc[mt][nt][3] + b1v, 0.f)) };
                    *(float2*)(pe + (size_t)(n0 + r_hi) * NF + col) = v;
                }
            }
        }
    }
}

// ---------------------------------------------------------------------------
// Edge encoder via mma.sync tf32 — ldmatrix fragment loads
// ---------------------------------------------------------------------------
#define EE_OFF_RECV 0
#define EE_OFF_SEND 512
#define EE_OFF_B1   1024
#define EE_OFF_B2   1536
#define EE_OFF_B3   2048
#define EE_OFF_W1   2560
#define EE_OFF_W2   (EE_OFF_W1 + 32768)
#define EE_OFF_W3   (EE_OFF_W2 + 65536)
#define EE_OFF_ACT  (EE_OFF_W3 + 65536)
#define EE_SMEM_BYTES (EE_OFF_ACT + 65536)

__global__ __launch_bounds__(256, 1) void k_edge_enc_mma(
    const float* __restrict__ attr, const float* __restrict__ state,
    const float* __restrict__ Ra,
    const int* __restrict__ recv, const int* __restrict__ send,
    const float* __restrict__ w1, const float* __restrict__ b1,
    const float* __restrict__ w2, const float* __restrict__ b2,
    const float* __restrict__ w3, const float* __restrict__ b3,
    float* __restrict__ ee, int e_cnt)
{
    extern __shared__ char smem[];
    int*      s_recv = (int*)     (smem + EE_OFF_RECV);
    int*      s_send = (int*)     (smem + EE_OFF_SEND);
    float*    s_b1   = (float*)   (smem + EE_OFF_B1);
    float*    s_b2   = (float*)   (smem + EE_OFF_B2);
    float*    s_b3   = (float*)   (smem + EE_OFF_B3);
    uint32_t* W1s    = (uint32_t*)(smem + EE_OFF_W1);   // transposed [128][64]
    uint32_t* W2s    = (uint32_t*)(smem + EE_OFF_W2);   // transposed [128][128]
    uint32_t* W3s    = (uint32_t*)(smem + EE_OFF_W3);   // transposed [128][128]
    const uint32_t sb = smem_u32(smem);
    const uint32_t actb = sb + EE_OFF_ACT;
    const uint32_t w1b  = sb + EE_OFF_W1;
    const uint32_t w2b  = sb + EE_OFF_W2;
    const uint32_t w3b  = sb + EE_OFF_W3;

    const int tid = threadIdx.x;
    const int wid = tid >> 5;
    const int lane = tid & 31;
    const int grp = lane >> 2;
    const int tg  = lane & 3;
    const int wm  = wid & 3;
    const int wn  = wid >> 2;
    const int l8  = lane & 7;
    const int lj1 = (lane >> 3) & 1;
    const int lj2 = lane >> 4;

    for (int idx = tid; idx < 64 * 128; idx += 256) {
        int k = idx >> 7, n = idx & 127;
        float v = (k < 60) ? w1[k * NF + n] : 0.f;
        W1s[WTS(n, k, 64)] = cvt_tf32(v);
    }
    for (int idx = tid; idx < 128 * 128; idx += 256) {
        int k = idx >> 7, n = idx & 127;
        W2s[WTS(n, k, 128)] = cvt_tf32(w2[k * NF + n]);
        W3s[WTS(n, k, 128)] = cvt_tf32(w3[k * NF + n]);
    }
    if (tid < 128) { s_b1[tid] = b1[tid]; s_b2[tid] = b2[tid]; s_b3[tid] = b3[tid]; }

    const int ntiles = (e_cnt + 127) >> 7;
    const int r_st   = tid >> 1;
    const int half   = tid & 1;

    float acc[2][8][4];

    __syncthreads();

    for (int tile = blockIdx.x; tile < ntiles; tile += gridDim.x) {
        const int e0 = tile << 7;
        if (tid < 128) {
            int e = e0 + tid;
            s_recv[tid] = (e < e_cnt) ? recv[e] : 0;
            s_send[tid] = (e < e_cnt) ? send[e] : 0;
        }
        __syncthreads();

        // gather [128 x 64] via cp.async (sources pre-rounded tf32)
        {
            int rv = s_recv[r_st], sv = s_send[r_st];
            int e  = e0 + r_st;
            bool ev = (e < e_cnt);
            if (half == 0) {
                const float* a_rv = attr + (size_t)rv * ATTR_W;
                const float* a_sv = attr + (size_t)sv * ATTR_W;
#pragma unroll
                for (int q = 0; q < 4; q++)
                    cp_async16(actb + 4 * ASW(r_st, q * 4), a_rv + q * 4, true);
#pragma unroll
                for (int q = 0; q < 4; q++)
                    cp_async16(actb + 4 * ASW(r_st, 16 + q * 4), a_sv + q * 4, true);
            } else {
                const float* s_rv = state + (size_t)rv * STATE_W;
                const float* s_sv = state + (size_t)sv * STATE_W;
#pragma unroll
                for (int q = 0; q < 3; q++)
                    cp_async16(actb + 4 * ASW(r_st, 32 + q * 4), s_rv + q * 4, true);
#pragma unroll
                for (int q = 0; q < 3; q++)
                    cp_async16(actb + 4 * ASW(r_st, 44 + q * 4), s_sv + q * 4, true);
                cp_async16(actb + 4 * ASW(r_st, 56), Ra + (size_t)(ev ? e : 0) * REL_W, ev);
                cp_async16(actb + 4 * ASW(r_st, 60), Ra, false);  // zfill pad
            }
            CP_COMMIT();
            CP_WAIT0();
        }
        __syncthreads();

        // layer 1 (k=64, W1 transposed stride 64)
#pragma unroll
        for (int mt = 0; mt < 2; mt++)
#pragma unroll
            for (int nt = 0; nt < 8; nt++)
#pragma unroll
                for (int i = 0; i < 4; i++) acc[mt][nt][i] = 0.f;
#pragma unroll
        for (int s = 0; s < 8; s++) {
            const int kk = s * 8;
            const int bk = (kk + lj1 * 4) ^ (l8 << 2);
            uint32_t bf[8][2];
#pragma unroll
            for (int nt = 0; nt < 8; nt++) {
                int nrow = wn * 64 + nt * 8 + l8;
                ldsm_x2(bf[nt], w1b + 4 * (nrow * 64 + bk));
            }
#pragma unroll
            for (int mt = 0; mt < 2; mt++) {
                int arow = wm * 32 + mt * 16 + l8 + lj1 * 8;
                int acol = (kk + lj2 * 4) ^ ((arow & 7) << 2);
                uint32_t af[4];
                ldsm_x4(af, actb + 4 * (arow * 128 + acol));
#pragma unroll
                for (int nt = 0; nt < 8; nt++)
                    mma_tf32(acc[mt][nt], af, bf[nt]);
            }
        }
        __syncthreads();

#pragma unroll
        for (int mt = 0; mt < 2; mt++) {
            int r_lo = wm * 32 + mt * 16 + grp;
            int r_hi = r_lo + 8;
#pragma unroll
            for (int nt = 0; nt < 8; nt++) {
                int col = wn * 64 + nt * 8 + tg * 2;
                float b0 = s_b1[col], b1v = s_b1[col + 1];
                uint2 lo = { cvt_tf32(fmaxf(acc[mt][nt][0] + b0, 0.f)),
                             cvt_tf32(fmaxf(acc[mt][nt][1] + b1v, 0.f)) };
                uint2 hi = { cvt_tf32(fmaxf(acc[mt][nt][2] + b0, 0.f)),
                             cvt_tf32(fmaxf(acc[mt][nt][3] + b1v, 0.f)) };
                *(uint2*)((uint32_t*)(smem + EE_OFF_ACT) + ASW(r_lo, col)) = lo;
                *(uint2*)((uint32_t*)(smem + EE_OFF_ACT) + ASW(r_hi, col)) = hi;
            }
        }
        __syncthreads();

        // layer 2 (k=128, W2 transposed stride 128)
#pragma unroll
        for (int mt = 0; mt < 2; mt++)
#pragma unroll
            for (int nt = 0; nt < 8; nt++)
#pragma unroll
                for (int i = 0; i < 4; i++) acc[mt][nt][i] = 0.f;
#pragma unroll
        for (int s = 0; s < 16; s++) {
            const int kk = s * 8;
            const int bk = (kk + lj1 * 4) ^ (l8 << 2);
            uint32_t bf[8][2];
#pragma unroll
            for (int nt = 0; nt < 8; nt++) {
                int nrow = wn * 64 + nt * 8 + l8;
                ldsm_x2(bf[nt], w2b + 4 * (nrow * 128 + bk));
            }
#pragma unroll
            for (int mt = 0; mt < 2; mt++) {
                int arow = wm * 32 + mt * 16 + l8 + lj1 * 8;
                int acol = (kk + lj2 * 4) ^ ((arow & 7) << 2);
                uint32_t af[4];
                ldsm_x4(af, actb + 4 * (arow * 128 + acol));
#pragma unroll
                for (int nt = 0; nt < 8; nt++)
                    mma_tf32(acc[mt][nt], af, bf[nt]);
            }
        }
        __syncthreads();

#pragma unroll
        for (int mt = 0; mt < 2; mt++) {
            int r_lo = wm * 32 + mt * 16 + grp;
            int r_hi = r_lo + 8;
#pragma unroll
            for (int nt = 0; nt < 8; nt++) {
                int col = wn * 64 + nt * 8 + tg * 2;
                float b0 = s_b2[col], b1v = s_b2[col + 1];
                uint2 lo = { cvt_tf32(fmaxf(acc[mt][nt][0] + b0, 0.f)),
                             cvt_tf32(fmaxf(acc[mt][nt][1] + b1v, 0.f)) };
                uint2 hi = { cvt_tf32(fmaxf(acc[mt][nt][2] + b0, 0.f)),
                             cvt_tf32(fmaxf(acc[mt][nt][3] + b1v, 0.f)) };
                *(uint2*)((uint32_t*)(smem + EE_OFF_ACT) + ASW(r_lo, col)) = lo;
                *(uint2*)((uint32_t*)(smem + EE_OFF_ACT) + ASW(r_hi, col)) = hi;
            }
        }
        __syncthreads();

        // layer 3 (k=128, W3 transposed) -> ee
#pragma unroll
        for (int mt = 0; mt < 2; mt++)
#pragma unroll
            for (int nt = 0; nt < 8; nt++)
#pragma unroll
                for (int i = 0; i < 4; i++) acc[mt][nt][i] = 0.f;
#pragma unroll
        for (int s = 0; s < 16; s++) {
            const int kk = s * 8;
            const int bk = (kk + lj1 * 4) ^ (l8 << 2);
            uint32_t bf[8][2];
#pragma unroll
            for (int nt = 0; nt < 8; nt++) {
                int nrow = wn * 64 + nt * 8 + l8;
                ldsm_x2(bf[nt], w3b + 4 * (nrow * 128 + bk));
            }
#pragma unroll
            for (int mt = 0; mt < 2; mt++) {
                int arow = wm * 32 + mt * 16 + l8 + lj1 * 8;
                int acol = (kk + lj2 * 4) ^ ((arow & 7) << 2);
                uint32_t af[4];
                ldsm_x4(af, actb + 4 * (arow * 128 + acol));
#pragma unroll
                for (int nt = 0; nt < 8; nt++)
                    mma_tf32(acc[mt][nt], af, bf[nt]);
            }
        }
        __syncthreads();

        // epilogue: ee = tf32(relu(acc + b3))
#pragma unroll
        for (int mt = 0; mt < 2; mt++) {
            int r_lo = wm * 32 + mt * 16 + grp;
            int r_hi = r_lo + 8;
            bool v_lo = (e0 + r_lo) < e_cnt;
            bool v_hi = (e0 + r_hi) < e_cnt;
#pragma unroll
            for (int nt = 0; nt < 8; nt++) {
                int col = wn * 64 + nt * 8 + tg * 2;
                float b0 = s_b3[col], b1v = s_b3[col + 1];
                if (v_lo) {
                    float2 v = { cvt_tf32f(fmaxf(acc[mt][nt][0] + b0, 0.f)),
                                 cvt_tf32f(fmaxf(acc[mt][nt][1] + b1v, 0.f)) };
                    *(float2*)(ee + (size_t)(e0 + r_lo) * NF + col) = v;
                }
                if (v_hi) {
                    float2 v = { cvt_tf32f(fmaxf(acc[mt][nt][2] + b0, 0.f)),
                                 cvt_tf32f(fmaxf(acc[mt][nt][3] + b1v, 0.f)) };
                    *(float2*)(ee + (size_t)(e0 + r_hi) * NF + col) = v;
                }
            }
        }
    }
}

// ---------------------------------------------------------------------------
// Relation propagator v7 (round-14, passing): ldmatrix loads, B transposed
// ---------------------------------------------------------------------------
#define RP2_OFF_RECV 0
#define RP2_OFF_SEND 512
#define RP2_OFF_BIAS 1024
#define RP2_OFF_A0   1536
#define RP2_OFF_A1   (RP2_OFF_A0 + 16384)
#define RP2_OFF_B    (RP2_OFF_A1 + 16384)
#define RP2_SMEM_BYTES (RP2_OFF_B + 384 * 128 * 4)

__global__ __launch_bounds__(256, 1) void k_rel_prop_mma(
    const float* __restrict__ ee, const float* __restrict__ eff,
    const int* __restrict__ recv, const int* __restrict__ send,
    const float* __restrict__ w, const float* __restrict__ b,
    float* __restrict__ agg, int e_cnt, int nch)
{
    extern __shared__ char smem[];
    int*      s_recv = (int*)     (smem + RP2_OFF_RECV);
    int*      s_send = (int*)     (smem + RP2_OFF_SEND);
    float*    s_bias = (float*)   (smem + RP2_OFF_BIAS);
    uint32_t* Bs     = (uint32_t*)(smem + RP2_OFF_B);     // transposed [128][384]
    const uint32_t sb = smem_u32(smem);
    const uint32_t a0b = sb + RP2_OFF_A0;
    const uint32_t a1b = sb + RP2_OFF_A1;
    const uint32_t btb = sb + RP2_OFF_B;

    const int tid = threadIdx.x;
    const int wid = tid >> 5;
    const int lane = tid & 31;
    const int grp = lane >> 2;
    const int tg  = lane & 3;
    const int wm  = wid & 3;
    const int wn  = wid >> 2;
    const int l8  = lane & 7;
    const int lj1 = (lane >> 3) & 1;
    const int lj2 = lane >> 4;
    const int bxor = l8 << 2;

    for (int idx = tid; idx < nch * 32 * 128; idx += 256) {
        int k = idx >> 7, n = idx & 127;
        Bs[WTS(n, k, 384)] = cvt_tf32(w[k * NF + n]);
    }
    if (tid < 128) s_bias[tid] = b[tid];
    __syncthreads();

    const int ntiles = (e_cnt + 127) >> 7;
    const int r_st   = tid >> 1;
    const int half   = tid & 1;

    for (int tile = blockIdx.x; tile < ntiles; tile += gridDim.x) {
        const int e0 = tile << 7;

        {
            int e = e0 + r_st;
            bool valid = (e < e_cnt);
            const float* src = ee + (size_t)(valid ? e : 0) * NF + half * 16;
#pragma unroll
            for (int q = 0; q < 4; q++)
                cp_async16(a0b + 4 * ACSW(r_st, half * 16 + q * 4), src + q * 4, valid);
            CP_COMMIT();
        }

        if (tid < 128) {
            int e = e0 + tid;
            s_recv[tid] = (e < e_cnt) ? recv[e] : 0;
            s_send[tid] = (e < e_cnt) ? send[e] : 0;
        }

        float acc[2][8][4];
#pragma unroll
        for (int mt = 0; mt < 2; mt++)
#pragma unroll
            for (int nt = 0; nt < 8; nt++)
#pragma unroll
                for (int i = 0; i < 4; i++) acc[mt][nt][i] = 0.f;

        __syncthreads();

        for (int c = 0; c < nch; c++) {
            CP_WAIT0();
            __syncthreads();

            if (c + 1 < nch) {
                int cn = c + 1;
                const float* src;
                bool valid = true;
                if (cn < 4) {
                    int e = e0 + r_st;
                    valid = (e < e_cnt);
                    src = ee + (size_t)(valid ? e : 0) * NF + cn * 32;
                } else if (cn < 8) {
                    src = eff + (size_t)s_recv[r_st] * NF + (cn - 4) * 32;
                } else {
                    src = eff + (size_t)s_send[r_st] * NF + (cn - 8) * 32;
                }
                uint32_t abase = (cn & 1) ? a1b : a0b;
#pragma unroll
                for (int q = 0; q < 4; q++)
                    cp_async16(abase + 4 * ACSW(r_st, half * 16 + q * 4),
                               src + half * 16 + q * 4, valid);
                CP_COMMIT();
            }

            const uint32_t abufb = (c & 1) ? a1b : a0b;
            const int kb = c * 32;
#pragma unroll
            for (int s = 0; s < 4; s++) {
                const int ac = s * 8;
                const int kk = kb + ac;
                const int bk = (kk + lj1 * 4) ^ bxor;
                uint32_t bf[8][2];
#pragma unroll
                for (int nt = 0; nt < 8; nt++) {
                    int nrow = wn * 64 + nt * 8 + l8;
                    ldsm_x2(bf[nt], btb + 4 * (nrow * 384 + bk));
                }
#pragma unroll
                for (int mt = 0; mt < 2; mt++) {
                    int arow = wm * 32 + mt * 16 + l8 + lj1 * 8;
                    int acol = (ac + lj2 * 4) ^ ((arow & 7) << 2);
                    uint32_t af[4];
                    ldsm_x4(af, abufb + 4 * (arow * 32 + acol));
#pragma unroll
                    for (int nt = 0; nt < 8; nt++)
                        mma_tf32(acc[mt][nt], af, bf[nt]);
                }
            }
        }

        // epilogue: bias + relu + red.v2 scatter
#pragma unroll
        for (int mt = 0; mt < 2; mt++) {
            int r_lo = wm * 32 + mt * 16 + grp;
            int r_hi = r_lo + 8;
            bool v_lo = (e0 + r_lo) < e_cnt;
            bool v_hi = (e0 + r_hi) < e_cnt;
            int d_lo = s_recv[r_lo];
            int d_hi = s_recv[r_hi];
#pragma unroll
            for (int nt = 0; nt < 8; nt++) {
                int col = wn * 64 + nt * 8 + tg * 2;
                float b0 = s_bias[col], b1 = s_bias[col + 1];
                if (v_lo)
                    red2(&agg[(size_t)d_lo * NF + col],
                         fmaxf(acc[mt][nt][0] + b0, 0.f),
                         fmaxf(acc[mt][nt][1] + b1, 0.f));
                if (v_hi)
                    red2(&agg[(size_t)d_hi * NF + col],
                         fmaxf(acc[mt][nt][2] + b0, 0.f),
                         fmaxf(acc[mt][nt][3] + b1, 0.f));
            }
        }
        __syncthreads();
    }
}

// ---------------------------------------------------------------------------
// Particle propagator — ldmatrix loads, B transposed [128][256]
// ---------------------------------------------------------------------------
#define PP_OFF_BIAS 0
#define PP_OFF_A0   512
#define PP_OFF_A1   (PP_OFF_A0 + 16384)
#define PP_OFF_B    (PP_OFF_A1 + 16384)
#define PP_SMEM_BYTES (PP_OFF_B + 256 * 128 * 4)

__global__ __launch_bounds__(256, 1) void k_part_prop_mma(
    const float* __restrict__ pe, const float* __restrict__ agg,
    const float* __restrict__ w, const float* __restrict__ b,
    float* __restrict__ eff, int n)
{
    extern __shared__ char smem[];
    float*    s_bias = (float*)   (smem + PP_OFF_BIAS);
    uint32_t* Bs     = (uint32_t*)(smem + PP_OFF_B);    // transposed [128][256]
    const uint32_t sb = smem_u32(smem);
    const uint32_t a0b = sb + PP_OFF_A0;
    const uint32_t a1b = sb + PP_OFF_A1;
    const uint32_t btb = sb + PP_OFF_B;

    const int tid = threadIdx.x;
    const int wid = tid >> 5;
    const int lane = tid & 31;
    const int grp = lane >> 2;
    const int tg  = lane & 3;
    const int wm  = wid & 3;
    const int wn  = wid >> 2;
    const int l8  = lane & 7;
    const int lj1 = (lane >> 3) & 1;
    const int lj2 = lane >> 4;
    const int bxor = l8 << 2;

    for (int idx = tid; idx < 256 * 128; idx += 256) {
        int k = idx >> 7, nn = idx & 127;
        Bs[WTS(nn, k, 256)] = cvt_tf32(w[k * NF + nn]);
    }
    if (tid < 128) s_bias[tid] = b[tid];
    __syncthreads();

    const int ntiles = (n + 127) >> 7;
    const int r_st   = tid >> 1;
    const int half   = tid & 1;

    for (int tile = blockIdx.x; tile < ntiles; tile += gridDim.x) {
        const int n0 = tile << 7;
        const int row = n0 + r_st;
        const bool rv = (row < n);
        const size_t rowc = (size_t)(rv ? row : 0);

        {
            const float* src = pe + rowc * NF + half * 16;
#pragma unroll
            for (int q = 0; q < 4; q++)
                cp_async16(a0b + 4 * ACSW(r_st, half * 16 + q * 4), src + q * 4, rv);
            CP_COMMIT();
        }

        float acc[2][8][4];
#pragma unroll
        for (int mt = 0; mt < 2; mt++)
#pragma unroll
            for (int nt = 0; nt < 8; nt++)
#pragma unroll
                for (int i = 0; i < 4; i++) acc[mt][nt][i] = 0.f;

        for (int c = 0; c < 8; c++) {
            CP_WAIT0();
            __syncthreads();

            if (c < 7) {
                int cn = c + 1;
                const float* src = (cn < 4) ? pe  + rowc * NF + cn * 32
                                            : agg + rowc * NF + (cn - 4) * 32;
                uint32_t abase = (cn & 1) ? a1b : a0b;
#pragma unroll
                for (int q = 0; q < 4; q++)
                    cp_async16(abase + 4 * ACSW(r_st, half * 16 + q * 4),
                               src + half * 16 + q * 4, rv);
                CP_COMMIT();
            }

            const uint32_t abufb = (c & 1) ? a1b : a0b;
            const int kb = c * 32;
#pragma unroll
            for (int s = 0; s < 4; s++) {
                const int ac = s * 8;
                const int kk = kb + ac;
                const int bk = (kk + lj1 * 4) ^ bxor;
                uint32_t bf[8][2];
#pragma unroll
                for (int nt = 0; nt < 8; nt++) {
                    int nrow = wn * 64 + nt * 8 + l8;
                    ldsm_x2(bf[nt], btb + 4 * (nrow * 256 + bk));
                }
#pragma unroll
                for (int mt = 0; mt < 2; mt++) {
                    int arow = wm * 32 + mt * 16 + l8 + lj1 * 8;
                    int acol = (ac + lj2 * 4) ^ ((arow & 7) << 2);
                    uint32_t af[4];
                    ldsm_x4(af, abufb + 4 * (arow * 32 + acol));
#pragma unroll
                    for (int nt = 0; nt < 8; nt++)
                        mma_tf32(acc[mt][nt], af, bf[nt]);
                }
            }
        }

        // epilogue: eff = tf32(relu(acc + b))
#pragma unroll
        for (int mt = 0; mt < 2; mt++) {
            int r_lo = wm * 32 + mt * 16 + grp;
            int r_hi = r_lo + 8;
            bool v_lo = (n0 + r_lo) < n;
            bool v_hi = (n0 + r_hi) < n;
#pragma unroll
            for (int nt = 0; nt < 8; nt++) {
                int col = wn * 64 + nt * 8 + tg * 2;
                float b0 = s_bias[col], b1 = s_bias[col + 1];
                if (v_lo) {
                    float2 v = { cvt_tf32f(fmaxf(acc[mt][nt][0] + b0, 0.f)),
                                 cvt_tf32f(fmaxf(acc[mt][nt][1] + b1, 0.f)) };
                    *(float2*)(eff + (size_t)(n0 + r_lo) * NF + col) = v;
                }
                if (v_hi) {
                    float2 v = { cvt_tf32f(fmaxf(acc[mt][nt][2] + b0, 0.f)),
                                 cvt_tf32f(fmaxf(acc[mt][nt][3] + b1, 0.f)) };
                    *(float2*)(eff + (size_t)(n0 + r_hi) * NF + col) = v;
                }
            }
        }
        __syncthreads();
    }
}

// ---------------------------------------------------------------------------
// Decoder — ldmatrix loads, W1/W2 transposed [128][128]
// ---------------------------------------------------------------------------
#define DE_OFF_B1   0
#define DE_OFF_B2   512
#define DE_OFF_B3   1024
#define DE_OFF_W3   1088
#define DE_OFF_W1   2624
#define DE_OFF_W2   (DE_OFF_W1 + 65536)
#define DE_OFF_ACT  (DE_OFF_W2 + 65536)
#define DE_SMEM_BYTES (DE_OFF_ACT + 65536)

__global__ __launch_bounds__(256, 1) void k_decoder_mma(
    const float* __restrict__ eff,
    const float* __restrict__ w1, const float* __restrict__ b1,
    const float* __restrict__ w2, const float* __restrict__ b2,
    const float* __restrict__ w3, const float* __restrict__ b3,
    float* __restrict__ out, int n)
{
    extern __shared__ char smem[];
    float*    s_b1 = (float*)   (smem + DE_OFF_B1);
    float*    s_b2 = (float*)   (smem + DE_OFF_B2);
    float*    s_b3 = (float*)   (smem + DE_OFF_B3);
    float*    s_w3 = (float*)   (smem + DE_OFF_W3);
    uint32_t* W1s  = (uint32_t*)(smem + DE_OFF_W1);   // transposed [128][128]
    uint32_t* W2s  = (uint32_t*)(smem + DE_OFF_W2);   // transposed [128][128]
    uint32_t* As   = (uint32_t*)(smem + DE_OFF_ACT);
    const uint32_t sb = smem_u32(smem);
    const uint32_t actb = sb + DE_OFF_ACT;
    const uint32_t w1b  = sb + DE_OFF_W1;
    const uint32_t w2b  = sb + DE_OFF_W2;

    const int tid = threadIdx.x;
    const int wid = tid >> 5;
    const int lane = tid & 31;
    const int grp = lane >> 2;
    const int tg  = lane & 3;
    const int wm  = wid & 3;
    const int wn  = wid >> 2;
    const int l8  = lane & 7;
    const int lj1 = (lane >> 3) & 1;
    const int lj2 = lane >> 4;

    for (int idx = tid; idx < 128 * 128; idx += 256) {
        int k = idx >> 7, nn = idx & 127;
        W1s[WTS(nn, k, 128)] = cvt_tf32(w1[k * NF + nn]);
        W2s[WTS(nn, k, 128)] = cvt_tf32(w2[k * NF + nn]);
    }
    for (int idx = tid; idx < 384; idx += 256) s_w3[idx] = w3[idx];
    if (tid < 128) { s_b1[tid] = b1[tid]; s_b2[tid] = b2[tid]; }
    if (tid < 3)   s_b3[tid] = b3[tid];
    __syncthreads();

    const int ntiles = (n + 127) >> 7;
    const int r_st   = tid >> 1;
    const int half   = tid & 1;

    float acc[2][8][4];

    for (int tile = blockIdx.x; tile < ntiles; tile += gridDim.x) {
        const int n0 = tile << 7;
        const int row = n0 + r_st;
        const bool rv = (row < n);

        {
            const float* src = eff + (size_t)(rv ? row : 0) * NF + half * 64;
#pragma unroll
            for (int q = 0; q < 16; q++)
                cp_async16(actb + 4 * ASW(r_st, half * 64 + q * 4), src + q * 4, rv);
            CP_COMMIT();
            CP_WAIT0();
        }
        __syncthreads();

        // layer 1 (W1 transposed)
#pragma unroll
        for (int mt = 0; mt < 2; mt++)
#pragma unroll
            for (int nt = 0; nt < 8; nt++)
#pragma unroll
                for (int i = 0; i < 4; i++) acc[mt][nt][i] = 0.f;
#pragma unroll
        for (int s = 0; s < 16; s++) {
            const int kk = s * 8;
            const int bk = (kk + lj1 * 4) ^ (l8 << 2);
            uint32_t bf[8][2];
#pragma unroll
            for (int nt = 0; nt < 8; nt++) {
                int nrow = wn * 64 + nt * 8 + l8;
                ldsm_x2(bf[nt], w1b + 4 * (nrow * 128 + bk));
            }
#pragma unroll
            for (int mt = 0; mt < 2; mt++) {
                int arow = wm * 32 + mt * 16 + l8 + lj1 * 8;
                int acol = (kk + lj2 * 4) ^ ((arow & 7) << 2);
                uint32_t af[4];
                ldsm_x4(af, actb + 4 * (arow * 128 + acol));
#pragma unroll
                for (int nt = 0; nt < 8; nt++)
                    mma_tf32(acc[mt][nt], af, bf[nt]);
            }
        }
        __syncthreads();

#pragma unroll
        for (int mt = 0; mt < 2; mt++) {
            int r_lo = wm * 32 + mt * 16 + grp;
            int r_hi = r_lo + 8;
#pragma unroll
            for (int nt = 0; nt < 8; nt++) {
                int col = wn * 64 + nt * 8 + tg * 2;
                float b0 = s_b1[col], b1v = s_b1[col + 1];
                uint2 lo = { cvt_tf32(fmaxf(acc[mt][nt][0] + b0, 0.f)),
                             cvt_tf32(fmaxf(acc[mt][nt][1] + b1v, 0.f)) };
                uint2 hi = { cvt_tf32(fmaxf(acc[mt][nt][2] + b0, 0.f)),
                             cvt_tf32(fmaxf(acc[mt][nt][3] + b1v, 0.f)) };
                *(uint2*)(As + ASW(r_lo, col)) = lo;
                *(uint2*)(As + ASW(r_hi, col)) = hi;
            }
        }
        __syncthreads();

        // layer 2 (W2 transposed)
#pragma unroll
        for (int mt = 0; mt < 2; mt++)
#pragma unroll
            for (int nt = 0; nt < 8; nt++)
#pragma unroll
                for (int i = 0; i < 4; i++) acc[mt][nt][i] = 0.f;
#pragma unroll
        for (int s = 0; s < 16; s++) {
            const int kk = s * 8;
            const int bk = (kk + lj1 * 4) ^ (l8 << 2);
            uint32_t bf[8][2];
#pragma unroll
            for (int nt = 0; nt < 8; nt++) {
                int nrow = wn * 64 + nt * 8 + l8;
                ldsm_x2(bf[nt], w2b + 4 * (nrow * 128 + bk));
            }
#pragma unroll
            for (int mt = 0; mt < 2; mt++) {
                int arow = wm * 32 + mt * 16 + l8 + lj1 * 8;
                int acol = (kk + lj2 * 4) ^ ((arow & 7) << 2);
                uint32_t af[4];
                ldsm_x4(af, actb + 4 * (arow * 128 + acol));
#pragma unroll
                for (int nt = 0; nt < 8; nt++)
                    mma_tf32(acc[mt][nt], af, bf[nt]);
            }
        }
        __syncthreads();

#pragma unroll
        for (int mt = 0; mt < 2; mt++) {
            int r_lo = wm * 32 + mt * 16 + grp;
            int r_hi = r_lo + 8;
#pragma unroll
            for (int nt = 0; nt < 8; nt++) {
                int col = wn * 64 + nt * 8 + tg * 2;
                float b0 = s_b2[col], b1v = s_b2[col + 1];
                uint2 lo = { __float_as_uint(fmaxf(acc[mt][nt][0] + b0, 0.f)),
                             __float_as_uint(fmaxf(acc[mt][nt][1] + b1v, 0.f)) };
                uint2 hi = { __float_as_uint(fmaxf(acc[mt][nt][2] + b0, 0.f)),
                             __float_as_uint(fmaxf(acc[mt][nt][3] + b1v, 0.f)) };
                *(uint2*)(As + ASW(r_lo, col)) = lo;
                *(uint2*)(As + ASW(r_hi, col)) = hi;
            }
        }
        __syncthreads();

        for (int d = tid; d < 128 * 3; d += 256) {
            int r = d / 3, j = d % 3;
            if (n0 + r < n) {
                float a = s_b3[j];
#pragma unroll 4
                for (int k = 0; k < NF; k++)
                    a = fmaf(__uint_as_float(As[ASW(r, k)]), s_w3[k * 3 + j], a);
                out[(size_t)(n0 + r) * 3 + j] = a;
            }
        }
        __syncthreads();
    }
}

// ---------------------------------------------------------------------------
// launch (round-12/14 structure)
// ---------------------------------------------------------------------------
extern "C" void kernel_launch(void* const* d_in, const int* in_sizes, int n_in,
                              void* d_out, int out_size)
{
    const float* attr  = (const float*)d_in[0];
    const float* state = (const float*)d_in[1];
    const float* Ra    = (const float*)d_in[2];
    const int*   recv  = (const int*)  d_in[3];
    const int*   send  = (const int*)  d_in[4];
    // d_in[5] = pstep (fixed 2)
    const float* pe_w1 = (const float*)d_in[6];
    const float* pe_b1 = (const float*)d_in[7];
    const float* pe_w2 = (const float*)d_in[8];
    const float* pe_b2 = (const float*)d_in[9];
    const float* ee_w1 = (const float*)d_in[10];
    const float* ee_b1 = (const float*)d_in[11];
    const float* ee_w2 = (const float*)d_in[12];
    const float* ee_b2 = (const float*)d_in[13];
    const float* ee_w3 = (const float*)d_in[14];
    const float* ee_b3 = (const float*)d_in[15];
    const float* rp_w  = (const float*)d_in[16];
    const float* rp_b  = (const float*)d_in[17];
    const float* pp_w  = (const float*)d_in[18];
    const float* pp_b  = (const float*)d_in[19];
    const float* de_w1 = (const float*)d_in[20];
    const float* de_b1 = (const float*)d_in[21];
    const float* de_w2 = (const float*)d_in[22];
    const float* de_b2 = (const float*)d_in[23];
    const float* de_w3 = (const float*)d_in[24];
    const float* de_b3 = (const float*)d_in[25];

    const int n = in_sizes[0] / ATTR_W;   // 100000
    const int e = in_sizes[2] / REL_W;    // 500000

    float *pe, *ee, *eff, *agg, *attr_r, *state_r, *ra_r;
    cudaGetSymbolAddress((void**)&pe,      g_pe);
    cudaGetSymbolAddress((void**)&ee,      g_ee);
    cudaGetSymbolAddress((void**)&eff,     g_eff);
    cudaGetSymbolAddress((void**)&agg,     g_agg);
    cudaGetSymbolAddress((void**)&attr_r,  g_attr_r);
    cudaGetSymbolAddress((void**)&state_r, g_state_r);
    cudaGetSymbolAddress((void**)&ra_r,    g_ra_r);

    cudaFuncSetAttribute(k_rel_prop_mma,
                         cudaFuncAttributeMaxDynamicSharedMemorySize, RP2_SMEM_BYTES);
    cudaFuncSetAttribute(k_edge_enc_mma,
                         cudaFuncAttributeMaxDynamicSharedMemorySize, EE_SMEM_BYTES);
    cudaFuncSetAttribute(k_part_prop_mma,
                         cudaFuncAttributeMaxDynamicSharedMemorySize, PP_SMEM_BYTES);
    cudaFuncSetAttribute(k_decoder_mma,
                         cudaFuncAttributeMaxDynamicSharedMemorySize, DE_SMEM_BYTES);
    cudaFuncSetAttribute(k_node_enc_mma,
                         cudaFuncAttributeMaxDynamicSharedMemorySize, NE_SMEM_BYTES);

    // pre-round inputs once (rna) so edge_enc's cp.async gather is exact
    k_round3<<<1024, 256>>>(attr, attr_r, n * ATTR_W,
                            state, state_r, n * STATE_W,
                            Ra, ra_r, e * REL_W);

    // encoders (no eff zero-fill needed: first rel_prop pass never reads eff)
    k_node_enc_mma<<<148, 256, NE_SMEM_BYTES>>>(attr, state, pe_w1, pe_b1, pe_w2, pe_b2, pe, n);
    k_edge_enc_mma<<<148, 256, EE_SMEM_BYTES>>>(attr_r, state_r, ra_r, recv, send,
                                                ee_w1, ee_b1, ee_w2, ee_b2, ee_w3, ee_b3, ee, e);

    // propagation (pstep = 2); iteration 0 has effect == 0 -> K=128 only
    for (int ps = 0; ps < PSTEP; ps++) {
        k_zero<<<1024, 256>>>((float4*)agg, n * NF / 4);
        k_rel_prop_mma<<<148, 256, RP2_SMEM_BYTES>>>(ee, eff, recv, send, rp_w, rp_b,
                                                     agg, e, (ps == 0) ? 4 : 12);
        k_part_prop_mma<<<148, 256, PP_SMEM_BYTES>>>(pe, agg, pp_w, pp_b, eff, n);
    }

    // decoder
    k_decoder_mma<<<148, 256, DE_SMEM_BYTES>>>(eff, de_w1, de_b1, de_w2, de_b2,
                                               de_w3, de_b3, (float*)d_out, n);
}

// round 16
// speedup vs baseline: 1.0225x; 1.0225x over previous
#include <cuda_runtime.h>
#include <cuda_bf16.h>
#include <cstdint>

// Problem constants (fixed by the dataset)
#define NN 100000
#define EE 500000
#define NF 128
#define ATTR_W 16
#define STATE_W 12
#define REL_W 4
#define PSTEP 2

// Scratch (device globals; no runtime allocation allowed)
__device__ float g_pe [NN * NF];
__device__ float g_ee [EE * NF];
__device__ float g_eff[NN * NF];
__device__ float g_agg[NN * NF];
__device__ float g_attr_r [NN * ATTR_W];   // tf32-pre-rounded inputs
__device__ float g_state_r[NN * STATE_W];
__device__ float g_ra_r   [EE * REL_W];

// ---------------------------------------------------------------------------
// helpers
// ---------------------------------------------------------------------------
__device__ __forceinline__ uint32_t cvt_tf32(float x) {
    uint32_t r;
    asm("cvt.rna.tf32.f32 %0, %1;" : "=r"(r) : "f"(x));
    return r;
}
__device__ __forceinline__ float cvt_tf32f(float x) {
    return __uint_as_float(cvt_tf32(x));
}

__device__ __forceinline__ void mma_tf32(float* c, const uint32_t* a, const uint32_t* b) {
    asm volatile(
        "mma.sync.aligned.m16n8k8.row.col.f32.tf32.tf32.f32 "
        "{%0,%1,%2,%3}, {%4,%5,%6,%7}, {%8,%9}, {%0,%1,%2,%3};"
        : "+f"(c[0]), "+f"(c[1]), "+f"(c[2]), "+f"(c[3])
        : "r"(a[0]), "r"(a[1]), "r"(a[2]), "r"(a[3]), "r"(b[0]), "r"(b[1]));
}

__device__ __forceinline__ void ldsm_x4(uint32_t* r, uint32_t addr) {
    asm volatile("ldmatrix.sync.aligned.m8n8.x4.shared.b16 {%0,%1,%2,%3}, [%4];"
                 : "=r"(r[0]), "=r"(r[1]), "=r"(r[2]), "=r"(r[3]) : "r"(addr));
}
__device__ __forceinline__ void ldsm_x2(uint32_t* r, uint32_t addr) {
    asm volatile("ldmatrix.sync.aligned.m8n8.x2.shared.b16 {%0,%1}, [%2];"
                 : "=r"(r[0]), "=r"(r[1]) : "r"(addr));
}

__device__ __forceinline__ void red2(float* p, float a, float b) {
    asm volatile("red.global.add.v2.f32 [%0], {%1, %2};" :: "l"(p), "f"(a), "f"(b) : "memory");
}

__device__ __forceinline__ uint32_t smem_u32(const void* p) {
    uint32_t a;
    asm("{ .reg .u64 t; cvta.to.shared.u64 t, %1; cvt.u32.u64 %0, t; }" : "=r"(a) : "l"(p));
    return a;
}

// 16-byte async copy, zero-fill when !valid
__device__ __forceinline__ void cp_async16(uint32_t dst, const float* src, bool valid) {
    int sz = valid ? 16 : 0;
    asm volatile("cp.async.ca.shared.global [%0], [%1], 16, %2;"
                 :: "r"(dst), "l"(src), "r"(sz) : "memory");
}
#define CP_COMMIT() asm volatile("cp.async.commit_group;" ::: "memory")
#define CP_WAIT0()  asm volatile("cp.async.wait_group 0;" ::: "memory")

// weight swizzle (k-major, for node_enc): addr = k*128 + (n ^ ((k&3)<<3))
#define WSW(k, n) (((k) << 7) + ((n) ^ (((k) & 3) << 3)))
// transposed weight swizzle, stride S floats: addr = n*S + (k ^ ((n&7)<<2))
#define WTS(nn, k, S) ((nn) * (S) + ((k) ^ (((nn) & 7) << 2)))
// activation swizzle (stride 128): addr = r*128 + (c ^ ((r&7)<<2))
#define ASW(r, c) (((r) << 7) + ((c) ^ (((r) & 7) << 2)))
// chunk swizzle (stride 32): addr = r*32 + (c ^ ((r&7)<<2)), c in 0..31
#define ACSW(r, c) (((r) << 5) + ((c) ^ (((r) & 7) << 2)))

// ---------------------------------------------------------------------------
// zero kernel (float4) and input pre-rounding
// ---------------------------------------------------------------------------
__global__ void k_zero(float4* p, int n4) {
    int i = blockIdx.x * blockDim.x + threadIdx.x;
    int stride = gridDim.x * blockDim.x;
    float4 z = make_float4(0.f, 0.f, 0.f, 0.f);
    for (; i < n4; i += stride) p[i] = z;
}

__global__ void k_round3(const float* __restrict__ a, float* __restrict__ ar, int na,
                         const float* __restrict__ s, float* __restrict__ sr, int ns,
                         const float* __restrict__ r, float* __restrict__ rr, int nr) {
    int i = blockIdx.x * blockDim.x + threadIdx.x;
    int stride = gridDim.x * blockDim.x;
    for (int j = i; j < na; j += stride) ar[j] = cvt_tf32f(a[j]);
    for (int j = i; j < ns; j += stride) sr[j] = cvt_tf32f(s[j]);
    for (int j = i; j < nr; j += stride) rr[j] = cvt_tf32f(r[j]);
}

// ---------------------------------------------------------------------------
// Node encoder via mma.sync tf32 (round-14/15 passing, unchanged)
// ---------------------------------------------------------------------------
#define NE_OFF_B1   0
#define NE_OFF_B2   512
#define NE_OFF_IN   1024
#define NE_OFF_W1   (NE_OFF_IN + 16384)
#define NE_OFF_W2   (NE_OFF_W1 + 16384)
#define NE_OFF_ACT  (NE_OFF_W2 + 65536)
#define NE_SMEM_BYTES (NE_OFF_ACT + 65536)

__global__ __launch_bounds__(256, 1) void k_node_enc_mma(
    const float* __restrict__ attr, const float* __restrict__ state,
    const float* __restrict__ w1, const float* __restrict__ b1,
    const float* __restrict__ w2, const float* __restrict__ b2,
    float* __restrict__ pe, int n)
{
    extern __shared__ char smem[];
    float*    s_b1 = (float*)   (smem + NE_OFF_B1);
    float*    s_b2 = (float*)   (smem + NE_OFF_B2);
    uint32_t* INs  = (uint32_t*)(smem + NE_OFF_IN);
    uint32_t* W1s  = (uint32_t*)(smem + NE_OFF_W1);
    uint32_t* W2s  = (uint32_t*)(smem + NE_OFF_W2);
    uint32_t* As   = (uint32_t*)(smem + NE_OFF_ACT);

    const int tid = threadIdx.x;
    const int wid = tid >> 5;
    const int lane = tid & 31;
    const int grp = lane >> 2;
    const int tg  = lane & 3;
    const int wm  = wid & 3;
    const int wn  = wid >> 2;

    for (int idx = tid; idx < 32 * 128; idx += 256) {
        int k = idx >> 7, nn = idx & 127;
        float v = (k < 28) ? w1[k * NF + nn] : 0.f;
        W1s[WSW(k, nn)] = cvt_tf32(v);
    }
    for (int idx = tid; idx < 128 * 128; idx += 256) {
        int k = idx >> 7, nn = idx & 127;
        W2s[WSW(k, nn)] = cvt_tf32(w2[k * NF + nn]);
    }
    if (tid < 128) { s_b1[tid] = b1[tid]; s_b2[tid] = b2[tid]; }
    __syncthreads();

    const int ntiles = (n + 127) >> 7;
    const int r_st   = tid >> 1;
    const int half   = tid & 1;

    float acc[2][8][4];

    for (int tile = blockIdx.x; tile < ntiles; tile += gridDim.x) {
        const int n0 = tile << 7;
        const int row = n0 + r_st;
        const bool rv = (row < n);

        if (half == 0) {
#pragma unroll
            for (int q = 0; q < 4; q++) {
                float4 v = rv ? *(const float4*)(attr + (size_t)row * ATTR_W + q * 4)
                              : make_float4(0.f, 0.f, 0.f, 0.f);
                uint4 u = { cvt_tf32(v.x), cvt_tf32(v.y), cvt_tf32(v.z), cvt_tf32(v.w) };
                *(uint4*)(INs + ACSW(r_st, q * 4)) = u;
            }
        } else {
#pragma unroll
            for (int q = 0; q < 3; q++) {
                float4 v = rv ? *(const float4*)(state + (size_t)row * STATE_W + q * 4)
                              : make_float4(0.f, 0.f, 0.f, 0.f);
                uint4 u = { cvt_tf32(v.x), cvt_tf32(v.y), cvt_tf32(v.z), cvt_tf32(v.w) };
                *(uint4*)(INs + ACSW(r_st, 16 + q * 4)) = u;
            }
            uint4 z = { 0u, 0u, 0u, 0u };
            *(uint4*)(INs + ACSW(r_st, 28)) = z;
        }
        __syncthreads();

        // layer 1 (k=32)
#pragma unroll
        for (int mt = 0; mt < 2; mt++)
#pragma unroll
            for (int nt = 0; nt < 8; nt++)
#pragma unroll
                for (int i = 0; i < 4; i++) acc[mt][nt][i] = 0.f;
#pragma unroll
        for (int s = 0; s < 4; s++) {
            const int kk = s * 8;
            uint32_t bf[8][2];
#pragma unroll
            for (int nt = 0; nt < 8; nt++) {
                int n_sw = (wn * 64 + nt * 8 + grp) ^ (tg << 3);
                bf[nt][0] = W1s[((kk + tg) << 7) + n_sw];
                bf[nt][1] = W1s[((kk + tg + 4) << 7) + n_sw];
            }
#pragma unroll
            for (int mt = 0; mt < 2; mt++) {
                int rb = wm * 32 + mt * 16;
                uint32_t af[4];
                af[0] = INs[ACSW(rb + grp,     kk + tg)];
                af[1] = INs[ACSW(rb + grp + 8, kk + tg)];
                af[2] = INs[ACSW(rb + grp,     kk + tg + 4)];
                af[3] = INs[ACSW(rb + grp + 8, kk + tg + 4)];
#pragma unroll
                for (int nt = 0; nt < 8; nt++)
                    mma_tf32(acc[mt][nt], af, bf[nt]);
            }
        }

        // h1 -> As
#pragma unroll
        for (int mt = 0; mt < 2; mt++) {
            int r_lo = wm * 32 + mt * 16 + grp;
            int r_hi = r_lo + 8;
#pragma unroll
            for (int nt = 0; nt < 8; nt++) {
                int col = wn * 64 + nt * 8 + tg * 2;
                float b0 = s_b1[col], b1v = s_b1[col + 1];
                uint2 lo = { cvt_tf32(fmaxf(acc[mt][nt][0] + b0, 0.f)),
                             cvt_tf32(fmaxf(acc[mt][nt][1] + b1v, 0.f)) };
                uint2 hi = { cvt_tf32(fmaxf(acc[mt][nt][2] + b0, 0.f)),
                             cvt_tf32(fmaxf(acc[mt][nt][3] + b1v, 0.f)) };
                *(uint2*)(As + ASW(r_lo, col)) = lo;
                *(uint2*)(As + ASW(r_hi, col)) = hi;
            }
        }
        __syncthreads();

        // layer 2 (k=128)
#pragma unroll
        for (int mt = 0; mt < 2; mt++)
#pragma unroll
            for (int nt = 0; nt < 8; nt++)
#pragma unroll
                for (int i = 0; i < 4; i++) acc[mt][nt][i] = 0.f;
#pragma unroll
        for (int s = 0; s < 16; s++) {
            const int kk = s * 8;
            uint32_t bf[8][2];
#pragma unroll
            for (int nt = 0; nt < 8; nt++) {
                int n_sw = (wn * 64 + nt * 8 + grp) ^ (tg << 3);
                bf[nt][0] = W2s[((kk + tg) << 7) + n_sw];
                bf[nt][1] = W2s[((kk + tg + 4) << 7) + n_sw];
            }
#pragma unroll
            for (int mt = 0; mt < 2; mt++) {
                int rb = wm * 32 + mt * 16;
                uint32_t af[4];
                af[0] = As[ASW(rb + grp,     kk + tg)];
                af[1] = As[ASW(rb + grp + 8, kk + tg)];
                af[2] = As[ASW(rb + grp,     kk + tg + 4)];
                af[3] = As[ASW(rb + grp + 8, kk + tg + 4)];
#pragma unroll
                for (int nt = 0; nt < 8; nt++)
                    mma_tf32(acc[mt][nt], af, bf[nt]);
            }
        }
        __syncthreads();

        // store pe (tf32-rounded)
#pragma unroll
        for (int mt = 0; mt < 2; mt++) {
            int r_lo = wm * 32 + mt * 16 + grp;
            int r_hi = r_lo + 8;
            bool v_lo = (n0 + r_lo) < n;
            bool v_hi = (n0 + r_hi) < n;
#pragma unroll
            for (int nt = 0; nt < 8; nt++) {
                int col = wn * 64 + nt * 8 + tg * 2;
                float b0 = s_b2[col], b1v = s_b2[col + 1];
                if (v_lo) {
                    float2 v = { cvt_tf32f(fmaxf(acc[mt][nt][0] + b0, 0.f)),
                                 cvt_tf32f(fmaxf(acc[mt][nt][1] + b1v, 0.f)) };
                    *(float2*)(pe + (size_t)(n0 + r_lo) * NF + col) = v;
                }
                if (v_hi) {
                    float2 v = { cvt_tf32f(fmaxf(acc[mt][nt][2] + b0, 0.f)),
                                 cvt_tf32f(fmaxf(acc[mt][nt][3] + b1v, 0.f)) };
                    *(float2*)(pe + (size_t)(n0 + r_hi) * NF + col) = v;
                }
            }
        }
    }
}

// ---------------------------------------------------------------------------
// Edge encoder via mma.sync tf32 (round-15 passing) — ldmatrix fragment loads
// ---------------------------------------------------------------------------
#define EE_OFF_RECV 0
#define EE_OFF_SEND 512
#define EE_OFF_B1   1024
#define EE_OFF_B2   1536
#define EE_OFF_B3   2048
#define EE_OFF_W1   2560
#define EE_OFF_W2   (EE_OFF_W1 + 32768)
#define EE_OFF_W3   (EE_OFF_W2 + 65536)
#define EE_OFF_ACT  (EE_OFF_W3 + 65536)
#define EE_SMEM_BYTES (EE_OFF_ACT + 65536)

__global__ __launch_bounds__(256, 1) void k_edge_enc_mma(
    const float* __restrict__ attr, const float* __restrict__ state,
    const float* __restrict__ Ra,
    const int* __restrict__ recv, const int* __restrict__ send,
    const float* __restrict__ w1, const float* __restrict__ b1,
    const float* __restrict__ w2, const float* __restrict__ b2,
    const float* __restrict__ w3, const float* __restrict__ b3,
    float* __restrict__ ee, int e_cnt)
{
    extern __shared__ char smem[];
    int*      s_recv = (int*)     (smem + EE_OFF_RECV);
    int*      s_send = (int*)     (smem + EE_OFF_SEND);
    float*    s_b1   = (float*)   (smem + EE_OFF_B1);
    float*    s_b2   = (float*)   (smem + EE_OFF_B2);
    float*    s_b3   = (float*)   (smem + EE_OFF_B3);
    uint32_t* W1s    = (uint32_t*)(smem + EE_OFF_W1);
    uint32_t* W2s    = (uint32_t*)(smem + EE_OFF_W2);
    uint32_t* W3s    = (uint32_t*)(smem + EE_OFF_W3);
    const uint32_t sb = smem_u32(smem);
    const uint32_t actb = sb + EE_OFF_ACT;
    const uint32_t w1b  = sb + EE_OFF_W1;
    const uint32_t w2b  = sb + EE_OFF_W2;
    const uint32_t w3b  = sb + EE_OFF_W3;

    const int tid = threadIdx.x;
    const int wid = tid >> 5;
    const int lane = tid & 31;
    const int grp = lane >> 2;
    const int tg  = lane & 3;
    const int wm  = wid & 3;
    const int wn  = wid >> 2;
    const int l8  = lane & 7;
    const int lj1 = (lane >> 3) & 1;
    const int lj2 = lane >> 4;

    for (int idx = tid; idx < 64 * 128; idx += 256) {
        int k = idx >> 7, n = idx & 127;
        float v = (k < 60) ? w1[k * NF + n] : 0.f;
        W1s[WTS(n, k, 64)] = cvt_tf32(v);
    }
    for (int idx = tid; idx < 128 * 128; idx += 256) {
        int k = idx >> 7, n = idx & 127;
        W2s[WTS(n, k, 128)] = cvt_tf32(w2[k * NF + n]);
        W3s[WTS(n, k, 128)] = cvt_tf32(w3[k * NF + n]);
    }
    if (tid < 128) { s_b1[tid] = b1[tid]; s_b2[tid] = b2[tid]; s_b3[tid] = b3[tid]; }

    const int ntiles = (e_cnt + 127) >> 7;
    const int r_st   = tid >> 1;
    const int half   = tid & 1;

    float acc[2][8][4];

    __syncthreads();

    for (int tile = blockIdx.x; tile < ntiles; tile += gridDim.x) {
        const int e0 = tile << 7;
        if (tid < 128) {
            int e = e0 + tid;
            s_recv[tid] = (e < e_cnt) ? recv[e] : 0;
            s_send[tid] = (e < e_cnt) ? send[e] : 0;
        }
        __syncthreads();

        // gather [128 x 64] via cp.async (sources pre-rounded tf32)
        {
            int rv = s_recv[r_st], sv = s_send[r_st];
            int e  = e0 + r_st;
            bool ev = (e < e_cnt);
            if (half == 0) {
                const float* a_rv = attr + (size_t)rv * ATTR_W;
                const float* a_sv = attr + (size_t)sv * ATTR_W;
#pragma unroll
                for (int q = 0; q < 4; q++)
                    cp_async16(actb + 4 * ASW(r_st, q * 4), a_rv + q * 4, true);
#pragma unroll
                for (int q = 0; q < 4; q++)
                    cp_async16(actb + 4 * ASW(r_st, 16 + q * 4), a_sv + q * 4, true);
            } else {
                const float* s_rv = state + (size_t)rv * STATE_W;
                const float* s_sv = state + (size_t)sv * STATE_W;
#pragma unroll
                for (int q = 0; q < 3; q++)
                    cp_async16(actb + 4 * ASW(r_st, 32 + q * 4), s_rv + q * 4, true);
#pragma unroll
                for (int q = 0; q < 3; q++)
                    cp_async16(actb + 4 * ASW(r_st, 44 + q * 4), s_sv + q * 4, true);
                cp_async16(actb + 4 * ASW(r_st, 56), Ra + (size_t)(ev ? e : 0) * REL_W, ev);
                cp_async16(actb + 4 * ASW(r_st, 60), Ra, false);  // zfill pad
            }
            CP_COMMIT();
            CP_WAIT0();
        }
        __syncthreads();

        // layer 1 (k=64, W1 transposed stride 64)
#pragma unroll
        for (int mt = 0; mt < 2; mt++)
#pragma unroll
            for (int nt = 0; nt < 8; nt++)
#pragma unroll
                for (int i = 0; i < 4; i++) acc[mt][nt][i] = 0.f;
#pragma unroll
        for (int s = 0; s < 8; s++) {
            const int kk = s * 8;
            const int bk = (kk + lj1 * 4) ^ (l8 << 2);
            uint32_t bf[8][2];
#pragma unroll
            for (int nt = 0; nt < 8; nt++) {
                int nrow = wn * 64 + nt * 8 + l8;
                ldsm_x2(bf[nt], w1b + 4 * (nrow * 64 + bk));
            }
#pragma unroll
            for (int mt = 0; mt < 2; mt++) {
                int arow = wm * 32 + mt * 16 + l8 + lj1 * 8;
                int acol = (kk + lj2 * 4) ^ ((arow & 7) << 2);
                uint32_t af[4];
                ldsm_x4(af, actb + 4 * (arow * 128 + acol));
#pragma unroll
                for (int nt = 0; nt < 8; nt++)
                    mma_tf32(acc[mt][nt], af, bf[nt]);
            }
        }
        __syncthreads();

#pragma unroll
        for (int mt = 0; mt < 2; mt++) {
            int r_lo = wm * 32 + mt * 16 + grp;
            int r_hi = r_lo + 8;
#pragma unroll
            for (int nt = 0; nt < 8; nt++) {
                int col = wn * 64 + nt * 8 + tg * 2;
                float b0 = s_b1[col], b1v = s_b1[col + 1];
                uint2 lo = { cvt_tf32(fmaxf(acc[mt][nt][0] + b0, 0.f)),
                             cvt_tf32(fmaxf(acc[mt][nt][1] + b1v, 0.f)) };
                uint2 hi = { cvt_tf32(fmaxf(acc[mt][nt][2] + b0, 0.f)),
                             cvt_tf32(fmaxf(acc[mt][nt][3] + b1v, 0.f)) };
                *(uint2*)((uint32_t*)(smem + EE_OFF_ACT) + ASW(r_lo, col)) = lo;
                *(uint2*)((uint32_t*)(smem + EE_OFF_ACT) + ASW(r_hi, col)) = hi;
            }
        }
        __syncthreads();

        // layer 2 (k=128, W2 transposed stride 128)
#pragma unroll
        for (int mt = 0; mt < 2; mt++)
#pragma unroll
            for (int nt = 0; nt < 8; nt++)
#pragma unroll
                for (int i = 0; i < 4; i++) acc[mt][nt][i] = 0.f;
#pragma unroll
        for (int s = 0; s < 16; s++) {
            const int kk = s * 8;
            const int bk = (kk + lj1 * 4) ^ (l8 << 2);
            uint32_t bf[8][2];
#pragma unroll
            for (int nt = 0; nt < 8; nt++) {
                int nrow = wn * 64 + nt * 8 + l8;
                ldsm_x2(bf[nt], w2b + 4 * (nrow * 128 + bk));
            }
#pragma unroll
            for (int mt = 0; mt < 2; mt++) {
                int arow = wm * 32 + mt * 16 + l8 + lj1 * 8;
                int acol = (kk + lj2 * 4) ^ ((arow & 7) << 2);
                uint32_t af[4];
                ldsm_x4(af, actb + 4 * (arow * 128 + acol));
#pragma unroll
                for (int nt = 0; nt < 8; nt++)
                    mma_tf32(acc[mt][nt], af, bf[nt]);
            }
        }
        __syncthreads();

#pragma unroll
        for (int mt = 0; mt < 2; mt++) {
            int r_lo = wm * 32 + mt * 16 + grp;
            int r_hi = r_lo + 8;
#pragma unroll
            for (int nt = 0; nt < 8; nt++) {
                int col = wn * 64 + nt * 8 + tg * 2;
                float b0 = s_b2[col], b1v = s_b2[col + 1];
                uint2 lo = { cvt_tf32(fmaxf(acc[mt][nt][0] + b0, 0.f)),
                             cvt_tf32(fmaxf(acc[mt][nt][1] + b1v, 0.f)) };
                uint2 hi = { cvt_tf32(fmaxf(acc[mt][nt][2] + b0, 0.f)),
                             cvt_tf32(fmaxf(acc[mt][nt][3] + b1v, 0.f)) };
                *(uint2*)((uint32_t*)(smem + EE_OFF_ACT) + ASW(r_lo, col)) = lo;
                *(uint2*)((uint32_t*)(smem + EE_OFF_ACT) + ASW(r_hi, col)) = hi;
            }
        }
        __syncthreads();

        // layer 3 (k=128, W3 transposed) -> ee
#pragma unroll
        for (int mt = 0; mt < 2; mt++)
#pragma unroll
            for (int nt = 0; nt < 8; nt++)
#pragma unroll
                for (int i = 0; i < 4; i++) acc[mt][nt][i] = 0.f;
#pragma unroll
        for (int s = 0; s < 16; s++) {
            const int kk = s * 8;
            const int bk = (kk + lj1 * 4) ^ (l8 << 2);
            uint32_t bf[8][2];
#pragma unroll
            for (int nt = 0; nt < 8; nt++) {
                int nrow = wn * 64 + nt * 8 + l8;
                ldsm_x2(bf[nt], w3b + 4 * (nrow * 128 + bk));
            }
#pragma unroll
            for (int mt = 0; mt < 2; mt++) {
                int arow = wm * 32 + mt * 16 + l8 + lj1 * 8;
                int acol = (kk + lj2 * 4) ^ ((arow & 7) << 2);
                uint32_t af[4];
                ldsm_x4(af, actb + 4 * (arow * 128 + acol));
#pragma unroll
                for (int nt = 0; nt < 8; nt++)
                    mma_tf32(acc[mt][nt], af, bf[nt]);
            }
        }
        __syncthreads();

        // epilogue: ee = tf32(relu(acc + b3))
#pragma unroll
        for (int mt = 0; mt < 2; mt++) {
            int r_lo = wm * 32 + mt * 16 + grp;
            int r_hi = r_lo + 8;
            bool v_lo = (e0 + r_lo) < e_cnt;
            bool v_hi = (e0 + r_hi) < e_cnt;
#pragma unroll
            for (int nt = 0; nt < 8; nt++) {
                int col = wn * 64 + nt * 8 + tg * 2;
                float b0 = s_b3[col], b1v = s_b3[col + 1];
                if (v_lo) {
                    float2 v = { cvt_tf32f(fmaxf(acc[mt][nt][0] + b0, 0.f)),
                                 cvt_tf32f(fmaxf(acc[mt][nt][1] + b1v, 0.f)) };
                    *(float2*)(ee + (size_t)(e0 + r_lo) * NF + col) = v;
                }
                if (v_hi) {
                    float2 v = { cvt_tf32f(fmaxf(acc[mt][nt][2] + b0, 0.f)),
                                 cvt_tf32f(fmaxf(acc[mt][nt][3] + b1v, 0.f)) };
                    *(float2*)(ee + (size_t)(e0 + r_hi) * NF + col) = v;
                }
            }
        }
    }
}

// ---------------------------------------------------------------------------
// Relation propagator (nch=12 path, round-14/15 passing): ldmatrix loads,
// B transposed, 1 CTA/SM
// ---------------------------------------------------------------------------
#define RP2_OFF_RECV 0
#define RP2_OFF_SEND 512
#define RP2_OFF_BIAS 1024
#define RP2_OFF_A0   1536
#define RP2_OFF_A1   (RP2_OFF_A0 + 16384)
#define RP2_OFF_B    (RP2_OFF_A1 + 16384)
#define RP2_SMEM_BYTES (RP2_OFF_B + 384 * 128 * 4)

__global__ __launch_bounds__(256, 1) void k_rel_prop_mma(
    const float* __restrict__ ee, const float* __restrict__ eff,
    const int* __restrict__ recv, const int* __restrict__ send,
    const float* __restrict__ w, const float* __restrict__ b,
    float* __restrict__ agg, int e_cnt)
{
    extern __shared__ char smem[];
    int*      s_recv = (int*)     (smem + RP2_OFF_RECV);
    int*      s_send = (int*)     (smem + RP2_OFF_SEND);
    float*    s_bias = (float*)   (smem + RP2_OFF_BIAS);
    uint32_t* Bs     = (uint32_t*)(smem + RP2_OFF_B);     // transposed [128][384]
    const uint32_t sb = smem_u32(smem);
    const uint32_t a0b = sb + RP2_OFF_A0;
    const uint32_t a1b = sb + RP2_OFF_A1;
    const uint32_t btb = sb + RP2_OFF_B;

    const int tid = threadIdx.x;
    const int wid = tid >> 5;
    const int lane = tid & 31;
    const int grp = lane >> 2;
    const int tg  = lane & 3;
    const int wm  = wid & 3;
    const int wn  = wid >> 2;
    const int l8  = lane & 7;
    const int lj1 = (lane >> 3) & 1;
    const int lj2 = lane >> 4;
    const int bxor = l8 << 2;

    for (int idx = tid; idx < 12 * 32 * 128; idx += 256) {
        int k = idx >> 7, n = idx & 127;
        Bs[WTS(n, k, 384)] = cvt_tf32(w[k * NF + n]);
    }
    if (tid < 128) s_bias[tid] = b[tid];
    __syncthreads();

    const int ntiles = (e_cnt + 127) >> 7;
    const int r_st   = tid >> 1;
    const int half   = tid & 1;

    for (int tile = blockIdx.x; tile < ntiles; tile += gridDim.x) {
        const int e0 = tile << 7;

        {
            int e = e0 + r_st;
            bool valid = (e < e_cnt);
            const float* src = ee + (size_t)(valid ? e : 0) * NF + half * 16;
#pragma unroll
            for (int q = 0; q < 4; q++)
                cp_async16(a0b + 4 * ACSW(r_st, half * 16 + q * 4), src + q * 4, valid);
            CP_COMMIT();
        }

        if (tid < 128) {
            int e = e0 + tid;
            s_recv[tid] = (e < e_cnt) ? recv[e] : 0;
            s_send[tid] = (e < e_cnt) ? send[e] : 0;
        }

        float acc[2][8][4];
#pragma unroll
        for (int mt = 0; mt < 2; mt++)
#pragma unroll
            for (int nt = 0; nt < 8; nt++)
#pragma unroll
                for (int i = 0; i < 4; i++) acc[mt][nt][i] = 0.f;

        __syncthreads();

        for (int c = 0; c < 12; c++) {
            CP_WAIT0();
            __syncthreads();

            if (c + 1 < 12) {
                int cn = c + 1;
                const float* src;
                bool valid = true;
                if (cn < 4) {
                    int e = e0 + r_st;
                    valid = (e < e_cnt);
                    src = ee + (size_t)(valid ? e : 0) * NF + cn * 32;
                } else if (cn < 8) {
                    src = eff + (size_t)s_recv[r_st] * NF + (cn - 4) * 32;
                } else {
                    src = eff + (size_t)s_send[r_st] * NF + (cn - 8) * 32;
                }
                uint32_t abase = (cn & 1) ? a1b : a0b;
#pragma unroll
                for (int q = 0; q < 4; q++)
                    cp_async16(abase + 4 * ACSW(r_st, half * 16 + q * 4),
                               src + half * 16 + q * 4, valid);
                CP_COMMIT();
            }

            const uint32_t abufb = (c & 1) ? a1b : a0b;
#pragma unroll
            for (int s = 0; s < 4; s++) {
                const int ac = s * 8;
                const int kk = c * 32 + ac;
                const int bk = (kk + lj1 * 4) ^ bxor;
                uint32_t bf[8][2];
#pragma unroll
                for (int nt = 0; nt < 8; nt++) {
                    int nrow = wn * 64 + nt * 8 + l8;
                    ldsm_x2(bf[nt], btb + 4 * (nrow * 384 + bk));
                }
#pragma unroll
                for (int mt = 0; mt < 2; mt++) {
                    int arow = wm * 32 + mt * 16 + l8 + lj1 * 8;
                    int acol = (ac + lj2 * 4) ^ ((arow & 7) << 2);
                    uint32_t af[4];
                    ldsm_x4(af, abufb + 4 * (arow * 32 + acol));
#pragma unroll
                    for (int nt = 0; nt < 8; nt++)
                        mma_tf32(acc[mt][nt], af, bf[nt]);
                }
            }
        }

        // epilogue: bias + relu + red.v2 scatter
#pragma unroll
        for (int mt = 0; mt < 2; mt++) {
            int r_lo = wm * 32 + mt * 16 + grp;
            int r_hi = r_lo + 8;
            bool v_lo = (e0 + r_lo) < e_cnt;
            bool v_hi = (e0 + r_hi) < e_cnt;
            int d_lo = s_recv[r_lo];
            int d_hi = s_recv[r_hi];
#pragma unroll
            for (int nt = 0; nt < 8; nt++) {
                int col = wn * 64 + nt * 8 + tg * 2;
                float b0 = s_bias[col], b1 = s_bias[col + 1];
                if (v_lo)
                    red2(&agg[(size_t)d_lo * NF + col],
                         fmaxf(acc[mt][nt][0] + b0, 0.f),
                         fmaxf(acc[mt][nt][1] + b1, 0.f));
                if (v_hi)
                    red2(&agg[(size_t)d_hi * NF + col],
                         fmaxf(acc[mt][nt][2] + b0, 0.f),
                         fmaxf(acc[mt][nt][3] + b1, 0.f));
            }
        }
        __syncthreads();
    }
}

// ---------------------------------------------------------------------------
// Relation propagator ps=0 (nch=4 compile-time): B only 64KB -> 2 CTAs/SM
// ---------------------------------------------------------------------------
#define RP4_OFF_B    RP2_OFF_B
#define RP4_SMEM_BYTES (RP4_OFF_B + 128 * 128 * 4)   // 34304 + 65536 = 99840

__global__ __launch_bounds__(256, 2) void k_rel_prop_mma4(
    const float* __restrict__ ee,
    const int* __restrict__ recv,
    const float* __restrict__ w, const float* __restrict__ b,
    float* __restrict__ agg, int e_cnt)
{
    extern __shared__ char smem[];
    int*      s_recv = (int*)     (smem + RP2_OFF_RECV);
    float*    s_bias = (float*)   (smem + RP2_OFF_BIAS);
    uint32_t* Bs     = (uint32_t*)(smem + RP4_OFF_B);     // transposed [128][128]
    const uint32_t sb = smem_u32(smem);
    const uint32_t a0b = sb + RP2_OFF_A0;
    const uint32_t a1b = sb + RP2_OFF_A1;
    const uint32_t btb = sb + RP4_OFF_B;

    const int tid = threadIdx.x;
    const int wid = tid >> 5;
    const int lane = tid & 31;
    const int grp = lane >> 2;
    const int tg  = lane & 3;
    const int wm  = wid & 3;
    const int wn  = wid >> 2;
    const int l8  = lane & 7;
    const int lj1 = (lane >> 3) & 1;
    const int lj2 = lane >> 4;
    const int bxor = l8 << 2;

    // stage B transposed [128 n][128 k]
    for (int idx = tid; idx < 128 * 128; idx += 256) {
        int k = idx >> 7, n = idx & 127;
        Bs[WTS(n, k, 128)] = cvt_tf32(w[k * NF + n]);
    }
    if (tid < 128) s_bias[tid] = b[tid];
    __syncthreads();

    const int ntiles = (e_cnt + 127) >> 7;
    const int r_st   = tid >> 1;
    const int half   = tid & 1;

    for (int tile = blockIdx.x; tile < ntiles; tile += gridDim.x) {
        const int e0 = tile << 7;

        {
            int e = e0 + r_st;
            bool valid = (e < e_cnt);
            const float* src = ee + (size_t)(valid ? e : 0) * NF + half * 16;
#pragma unroll
            for (int q = 0; q < 4; q++)
                cp_async16(a0b + 4 * ACSW(r_st, half * 16 + q * 4), src + q * 4, valid);
            CP_COMMIT();
        }

        if (tid < 128) {
            int e = e0 + tid;
            s_recv[tid] = (e < e_cnt) ? recv[e] : 0;
        }

        float acc[2][8][4];
#pragma unroll
        for (int mt = 0; mt < 2; mt++)
#pragma unroll
            for (int nt = 0; nt < 8; nt++)
#pragma unroll
                for (int i = 0; i < 4; i++) acc[mt][nt][i] = 0.f;

        __syncthreads();

#pragma unroll 1
        for (int c = 0; c < 4; c++) {
            CP_WAIT0();
            __syncthreads();

            if (c + 1 < 4) {
                int cn = c + 1;
                int e = e0 + r_st;
                bool valid = (e < e_cnt);
                const float* src = ee + (size_t)(valid ? e : 0) * NF + cn * 32;
                uint32_t abase = (cn & 1) ? a1b : a0b;
#pragma unroll
                for (int q = 0; q < 4; q++)
                    cp_async16(abase + 4 * ACSW(r_st, half * 16 + q * 4),
                               src + half * 16 + q * 4, valid);
                CP_COMMIT();
            }

            const uint32_t abufb = (c & 1) ? a1b : a0b;
#pragma unroll
            for (int s = 0; s < 4; s++) {
                const int ac = s * 8;
                const int kk = c * 32 + ac;
                const int bk = (kk + lj1 * 4) ^ bxor;
                uint32_t bf[8][2];
#pragma unroll
                for (int nt = 0; nt < 8; nt++) {
                    int nrow = wn * 64 + nt * 8 + l8;
                    ldsm_x2(bf[nt], btb + 4 * (nrow * 128 + bk));
                }
#pragma unroll
                for (int mt = 0; mt < 2; mt++) {
                    int arow = wm * 32 + mt * 16 + l8 + lj1 * 8;
                    int acol = (ac + lj2 * 4) ^ ((arow & 7) << 2);
                    uint32_t af[4];
                    ldsm_x4(af, abufb + 4 * (arow * 32 + acol));
#pragma unroll
                    for (int nt = 0; nt < 8; nt++)
                        mma_tf32(acc[mt][nt], af, bf[nt]);
                }
            }
        }

        // epilogue: bias + relu + red.v2 scatter
#pragma unroll
        for (int mt = 0; mt < 2; mt++) {
            int r_lo = wm * 32 + mt * 16 + grp;
            int r_hi = r_lo + 8;
            bool v_lo = (e0 + r_lo) < e_cnt;
            bool v_hi = (e0 + r_hi) < e_cnt;
            int d_lo = s_recv[r_lo];
            int d_hi = s_recv[r_hi];
#pragma unroll
            for (int nt = 0; nt < 8; nt++) {
                int col = wn * 64 + nt * 8 + tg * 2;
                float b0 = s_bias[col], b1 = s_bias[col + 1];
                if (v_lo)
                    red2(&agg[(size_t)d_lo * NF + col],
                         fmaxf(acc[mt][nt][0] + b0, 0.f),
                         fmaxf(acc[mt][nt][1] + b1, 0.f));
                if (v_hi)
                    red2(&agg[(size_t)d_hi * NF + col],
                         fmaxf(acc[mt][nt][2] + b0, 0.f),
                         fmaxf(acc[mt][nt][3] + b1, 0.f));
            }
        }
        __syncthreads();
    }
}

// ---------------------------------------------------------------------------
// Particle propagator (round-15 passing) — ldmatrix loads, B transposed
// ---------------------------------------------------------------------------
#define PP_OFF_BIAS 0
#define PP_OFF_A0   512
#define PP_OFF_A1   (PP_OFF_A0 + 16384)
#define PP_OFF_B    (PP_OFF_A1 + 16384)
#define PP_SMEM_BYTES (PP_OFF_B + 256 * 128 * 4)

__global__ __launch_bounds__(256, 1) void k_part_prop_mma(
    const float* __restrict__ pe, const float* __restrict__ agg,
    const float* __restrict__ w, const float* __restrict__ b,
    float* __restrict__ eff, int n)
{
    extern __shared__ char smem[];
    float*    s_bias = (float*)   (smem + PP_OFF_BIAS);
    uint32_t* Bs     = (uint32_t*)(smem + PP_OFF_B);    // transposed [128][256]
    const uint32_t sb = smem_u32(smem);
    const uint32_t a0b = sb + PP_OFF_A0;
    const uint32_t a1b = sb + PP_OFF_A1;
    const uint32_t btb = sb + PP_OFF_B;

    const int tid = threadIdx.x;
    const int wid = tid >> 5;
    const int lane = tid & 31;
    const int grp = lane >> 2;
    const int tg  = lane & 3;
    const int wm  = wid & 3;
    const int wn  = wid >> 2;
    const int l8  = lane & 7;
    const int lj1 = (lane >> 3) & 1;
    const int lj2 = lane >> 4;
    const int bxor = l8 << 2;

    for (int idx = tid; idx < 256 * 128; idx += 256) {
        int k = idx >> 7, nn = idx & 127;
        Bs[WTS(nn, k, 256)] = cvt_tf32(w[k * NF + nn]);
    }
    if (tid < 128) s_bias[tid] = b[tid];
    __syncthreads();

    const int ntiles = (n + 127) >> 7;
    const int r_st   = tid >> 1;
    const int half   = tid & 1;

    for (int tile = blockIdx.x; tile < ntiles; tile += gridDim.x) {
        const int n0 = tile << 7;
        const int row = n0 + r_st;
        const bool rv = (row < n);
        const size_t rowc = (size_t)(rv ? row : 0);

        {
            const float* src = pe + rowc * NF + half * 16;
#pragma unroll
            for (int q = 0; q < 4; q++)
                cp_async16(a0b + 4 * ACSW(r_st, half * 16 + q * 4), src + q * 4, rv);
            CP_COMMIT();
        }

        float acc[2][8][4];
#pragma unroll
        for (int mt = 0; mt < 2; mt++)
#pragma unroll
            for (int nt = 0; nt < 8; nt++)
#pragma unroll
                for (int i = 0; i < 4; i++) acc[mt][nt][i] = 0.f;

        for (int c = 0; c < 8; c++) {
            CP_WAIT0();
            __syncthreads();

            if (c < 7) {
                int cn = c + 1;
                const float* src = (cn < 4) ? pe  + rowc * NF + cn * 32
                                            : agg + rowc * NF + (cn - 4) * 32;
                uint32_t abase = (cn & 1) ? a1b : a0b;
#pragma unroll
                for (int q = 0; q < 4; q++)
                    cp_async16(abase + 4 * ACSW(r_st, half * 16 + q * 4),
                               src + half * 16 + q * 4, rv);
                CP_COMMIT();
            }

            const uint32_t abufb = (c & 1) ? a1b : a0b;
            const int kb = c * 32;
#pragma unroll
            for (int s = 0; s < 4; s++) {
                const int ac = s * 8;
                const int kk = kb + ac;
                const int bk = (kk + lj1 * 4) ^ bxor;
                uint32_t bf[8][2];
#pragma unroll
                for (int nt = 0; nt < 8; nt++) {
                    int nrow = wn * 64 + nt * 8 + l8;
                    ldsm_x2(bf[nt], btb + 4 * (nrow * 256 + bk));
                }
#pragma unroll
                for (int mt = 0; mt < 2; mt++) {
                    int arow = wm * 32 + mt * 16 + l8 + lj1 * 8;
                    int acol = (ac + lj2 * 4) ^ ((arow & 7) << 2);
                    uint32_t af[4];
                    ldsm_x4(af, abufb + 4 * (arow * 32 + acol));
#pragma unroll
                    for (int nt = 0; nt < 8; nt++)
                        mma_tf32(acc[mt][nt], af, bf[nt]);
                }
            }
        }

        // epilogue: eff = tf32(relu(acc + b))
#pragma unroll
        for (int mt = 0; mt < 2; mt++) {
            int r_lo = wm * 32 + mt * 16 + grp;
            int r_hi = r_lo + 8;
            bool v_lo = (n0 + r_lo) < n;
            bool v_hi = (n0 + r_hi) < n;
#pragma unroll
            for (int nt = 0; nt < 8; nt++) {
                int col = wn * 64 + nt * 8 + tg * 2;
                float b0 = s_bias[col], b1 = s_bias[col + 1];
                if (v_lo) {
                    float2 v = { cvt_tf32f(fmaxf(acc[mt][nt][0] + b0, 0.f)),
                                 cvt_tf32f(fmaxf(acc[mt][nt][1] + b1, 0.f)) };
                    *(float2*)(eff + (size_t)(n0 + r_lo) * NF + col) = v;
                }
                if (v_hi) {
                    float2 v = { cvt_tf32f(fmaxf(acc[mt][nt][2] + b0, 0.f)),
                                 cvt_tf32f(fmaxf(acc[mt][nt][3] + b1, 0.f)) };
                    *(float2*)(eff + (size_t)(n0 + r_hi) * NF + col) = v;
                }
            }
        }
        __syncthreads();
    }
}

// ---------------------------------------------------------------------------
// Decoder (round-15 passing) — ldmatrix loads, W1/W2 transposed
// ---------------------------------------------------------------------------
#define DE_OFF_B1   0
#define DE_OFF_B2   512
#define DE_OFF_B3   1024
#define DE_OFF_W3   1088
#define DE_OFF_W1   2624
#define DE_OFF_W2   (DE_OFF_W1 + 65536)
#define DE_OFF_ACT  (DE_OFF_W2 + 65536)
#define DE_SMEM_BYTES (DE_OFF_ACT + 65536)

__global__ __launch_bounds__(256, 1) void k_decoder_mma(
    const float* __restrict__ eff,
    const float* __restrict__ w1, const float* __restrict__ b1,
    const float* __restrict__ w2, const float* __restrict__ b2,
    const float* __restrict__ w3, const float* __restrict__ b3,
    float* __restrict__ out, int n)
{
    extern __shared__ char smem[];
    float*    s_b1 = (float*)   (smem + DE_OFF_B1);
    float*    s_b2 = (float*)   (smem + DE_OFF_B2);
    float*    s_b3 = (float*)   (smem + DE_OFF_B3);
    float*    s_w3 = (float*)   (smem + DE_OFF_W3);
    uint32_t* W1s  = (uint32_t*)(smem + DE_OFF_W1);
    uint32_t* W2s  = (uint32_t*)(smem + DE_OFF_W2);
    uint32_t* As   = (uint32_t*)(smem + DE_OFF_ACT);
    const uint32_t sb = smem_u32(smem);
    const uint32_t actb = sb + DE_OFF_ACT;
    const uint32_t w1b  = sb + DE_OFF_W1;
    const uint32_t w2b  = sb + DE_OFF_W2;

    const int tid = threadIdx.x;
    const int wid = tid >> 5;
    const int lane = tid & 31;
    const int grp = lane >> 2;
    const int tg  = lane & 3;
    const int wm  = wid & 3;
    const int wn  = wid >> 2;
    const int l8  = lane & 7;
    const int lj1 = (lane >> 3) & 1;
    const int lj2 = lane >> 4;

    for (int idx = tid; idx < 128 * 128; idx += 256) {
        int k = idx >> 7, nn = idx & 127;
        W1s[WTS(nn, k, 128)] = cvt_tf32(w1[k * NF + nn]);
        W2s[WTS(nn, k, 128)] = cvt_tf32(w2[k * NF + nn]);
    }
    for (int idx = tid; idx < 384; idx += 256) s_w3[idx] = w3[idx];
    if (tid < 128) { s_b1[tid] = b1[tid]; s_b2[tid] = b2[tid]; }
    if (tid < 3)   s_b3[tid] = b3[tid];
    __syncthreads();

    const int ntiles = (n + 127) >> 7;
    const int r_st   = tid >> 1;
    const int half   = tid & 1;

    float acc[2][8][4];

    for (int tile = blockIdx.x; tile < ntiles; tile += gridDim.x) {
        const int n0 = tile << 7;
        const int row = n0 + r_st;
        const bool rv = (row < n);

        {
            const float* src = eff + (size_t)(rv ? row : 0) * NF + half * 64;
#pragma unroll
            for (int q = 0; q < 16; q++)
                cp_async16(actb + 4 * ASW(r_st, half * 64 + q * 4), src + q * 4, rv);
            CP_COMMIT();
            CP_WAIT0();
        }
        __syncthreads();

        // layer 1 (W1 transposed)
#pragma unroll
        for (int mt = 0; mt < 2; mt++)
#pragma unroll
            for (int nt = 0; nt < 8; nt++)
#pragma unroll
                for (int i = 0; i < 4; i++) acc[mt][nt][i] = 0.f;
#pragma unroll
        for (int s = 0; s < 16; s++) {
            const int kk = s * 8;
            const int bk = (kk + lj1 * 4) ^ (l8 << 2);
            uint32_t bf[8][2];
#pragma unroll
            for (int nt = 0; nt < 8; nt++) {
                int nrow = wn * 64 + nt * 8 + l8;
                ldsm_x2(bf[nt], w1b + 4 * (nrow * 128 + bk));
            }
#pragma unroll
            for (int mt = 0; mt < 2; mt++) {
                int arow = wm * 32 + mt * 16 + l8 + lj1 * 8;
                int acol = (kk + lj2 * 4) ^ ((arow & 7) << 2);
                uint32_t af[4];
                ldsm_x4(af, actb + 4 * (arow * 128 + acol));
#pragma unroll
                for (int nt = 0; nt < 8; nt++)
                    mma_tf32(acc[mt][nt], af, bf[nt]);
            }
        }
        __syncthreads();

#pragma unroll
        for (int mt = 0; mt < 2; mt++) {
            int r_lo = wm * 32 + mt * 16 + grp;
            int r_hi = r_lo + 8;
#pragma unroll
            for (int nt = 0; nt < 8; nt++) {
                int col = wn * 64 + nt * 8 + tg * 2;
                float b0 = s_b1[col], b1v = s_b1[col + 1];
                uint2 lo = { cvt_tf32(fmaxf(acc[mt][nt][0] + b0, 0.f)),
                             cvt_tf32(fmaxf(acc[mt][nt][1] + b1v, 0.f)) };
                uint2 hi = { cvt_tf32(fmaxf(acc[mt][nt][2] + b0, 0.f)),
                             cvt_tf32(fmaxf(acc[mt][nt][3] + b1v, 0.f)) };
                *(uint2*)(As + ASW(r_lo, col)) = lo;
                *(uint2*)(As + ASW(r_hi, col)) = hi;
            }
        }
        __syncthreads();

        // layer 2 (W2 transposed)
#pragma unroll
        for (int mt = 0; mt < 2; mt++)
#pragma unroll
            for (int nt = 0; nt < 8; nt++)
#pragma unroll
                for (int i = 0; i < 4; i++) acc[mt][nt][i] = 0.f;
#pragma unroll
        for (int s = 0; s < 16; s++) {
            const int kk = s * 8;
            const int bk = (kk + lj1 * 4) ^ (l8 << 2);
            uint32_t bf[8][2];
#pragma unroll
            for (int nt = 0; nt < 8; nt++) {
                int nrow = wn * 64 + nt * 8 + l8;
                ldsm_x2(bf[nt], w2b + 4 * (nrow * 128 + bk));
            }
#pragma unroll
            for (int mt = 0; mt < 2; mt++) {
                int arow = wm * 32 + mt * 16 + l8 + lj1 * 8;
                int acol = (kk + lj2 * 4) ^ ((arow & 7) << 2);
                uint32_t af[4];
                ldsm_x4(af, actb + 4 * (arow * 128 + acol));
#pragma unroll
                for (int nt = 0; nt < 8; nt++)
                    mma_tf32(acc[mt][nt], af, bf[nt]);
            }
        }
        __syncthreads();

#pragma unroll
        for (int mt = 0; mt < 2; mt++) {
            int r_lo = wm * 32 + mt * 16 + grp;
            int r_hi = r_lo + 8;
#pragma unroll
            for (int nt = 0; nt < 8; nt++) {
                int col = wn * 64 + nt * 8 + tg * 2;
                float b0 = s_b2[col], b1v = s_b2[col + 1];
                uint2 lo = { __float_as_uint(fmaxf(acc[mt][nt][0] + b0, 0.f)),
                             __float_as_uint(fmaxf(acc[mt][nt][1] + b1v, 0.f)) };
                uint2 hi = { __float_as_uint(fmaxf(acc[mt][nt][2] + b0, 0.f)),
                             __float_as_uint(fmaxf(acc[mt][nt][3] + b1v, 0.f)) };
                *(uint2*)(As + ASW(r_lo, col)) = lo;
                *(uint2*)(As + ASW(r_hi, col)) = hi;
            }
        }
        __syncthreads();

        for (int d = tid; d < 128 * 3; d += 256) {
            int r = d / 3, j = d % 3;
            if (n0 + r < n) {
                float a = s_b3[j];
#pragma unroll 4
                for (int k = 0; k < NF; k++)
                    a = fmaf(__uint_as_float(As[ASW(r, k)]), s_w3[k * 3 + j], a);
                out[(size_t)(n0 + r) * 3 + j] = a;
            }
        }
        __syncthreads();
    }
}

// ---------------------------------------------------------------------------
// launch
// ---------------------------------------------------------------------------
extern "C" void kernel_launch(void* const* d_in, const int* in_sizes, int n_in,
                              void* d_out, int out_size)
{
    const float* attr  = (const float*)d_in[0];
    const float* state = (const float*)d_in[1];
    const float* Ra    = (const float*)d_in[2];
    const int*   recv  = (const int*)  d_in[3];
    const int*   send  = (const int*)  d_in[4];
    // d_in[5] = pstep (fixed 2)
    const float* pe_w1 = (const float*)d_in[6];
    const float* pe_b1 = (const float*)d_in[7];
    const float* pe_w2 = (const float*)d_in[8];
    const float* pe_b2 = (const float*)d_in[9];
    const float* ee_w1 = (const float*)d_in[10];
    const float* ee_b1 = (const float*)d_in[11];
    const float* ee_w2 = (const float*)d_in[12];
    const float* ee_b2 = (const float*)d_in[13];
    const float* ee_w3 = (const float*)d_in[14];
    const float* ee_b3 = (const float*)d_in[15];
    const float* rp_w  = (const float*)d_in[16];
    const float* rp_b  = (const float*)d_in[17];
    const float* pp_w  = (const float*)d_in[18];
    const float* pp_b  = (const float*)d_in[19];
    const float* de_w1 = (const float*)d_in[20];
    const float* de_b1 = (const float*)d_in[21];
    const float* de_w2 = (const float*)d_in[22];
    const float* de_b2 = (const float*)d_in[23];
    const float* de_w3 = (const float*)d_in[24];
    const float* de_b3 = (const float*)d_in[25];

    const int n = in_sizes[0] / ATTR_W;   // 100000
    const int e = in_sizes[2] / REL_W;    // 500000

    float *pe, *ee, *eff, *agg, *attr_r, *state_r, *ra_r;
    cudaGetSymbolAddress((void**)&pe,      g_pe);
    cudaGetSymbolAddress((void**)&ee,      g_ee);
    cudaGetSymbolAddress((void**)&eff,     g_eff);
    cudaGetSymbolAddress((void**)&agg,     g_agg);
    cudaGetSymbolAddress((void**)&attr_r,  g_attr_r);
    cudaGetSymbolAddress((void**)&state_r, g_state_r);
    cudaGetSymbolAddress((void**)&ra_r,    g_ra_r);

    cudaFuncSetAttribute(k_rel_prop_mma,
                         cudaFuncAttributeMaxDynamicSharedMemorySize, RP2_SMEM_BYTES);
    cudaFuncSetAttribute(k_rel_prop_mma4,
                         cudaFuncAttributeMaxDynamicSharedMemorySize, RP4_SMEM_BYTES);
    cudaFuncSetAttribute(k_edge_enc_mma,
                         cudaFuncAttributeMaxDynamicSharedMemorySize, EE_SMEM_BYTES);
    cudaFuncSetAttribute(k_part_prop_mma,
                         cudaFuncAttributeMaxDynamicSharedMemorySize, PP_SMEM_BYTES);
    cudaFuncSetAttribute(k_decoder_mma,
                         cudaFuncAttributeMaxDynamicSharedMemorySize, DE_SMEM_BYTES);
    cudaFuncSetAttribute(k_node_enc_mma,
                         cudaFuncAttributeMaxDynamicSharedMemorySize, NE_SMEM_BYTES);

    // pre-round inputs once (rna) so edge_enc's cp.async gather is exact
    k_round3<<<1024, 256>>>(attr, attr_r, n * ATTR_W,
                            state, state_r, n * STATE_W,
                            Ra, ra_r, e * REL_W);

    // encoders (no eff zero-fill needed: first rel_prop pass never reads eff)
    k_node_enc_mma<<<148, 256, NE_SMEM_BYTES>>>(attr, state, pe_w1, pe_b1, pe_w2, pe_b2, pe, n);
    k_edge_enc_mma<<<148, 256, EE_SMEM_BYTES>>>(attr_r, state_r, ra_r, recv, send,
                                                ee_w1, ee_b1, ee_w2, ee_b2, ee_w3, ee_b3, ee, e);

    // propagation step 0: effect == 0 -> K=128 only, 2 CTAs/SM kernel
    k_zero<<<1024, 256>>>((float4*)agg, n * NF / 4);
    k_rel_prop_mma4<<<296, 256, RP4_SMEM_BYTES>>>(ee, recv, rp_w, rp_b, agg, e);
    k_part_prop_mma<<<148, 256, PP_SMEM_BYTES>>>(pe, agg, pp_w, pp_b, eff, n);

    // propagation step 1: full K=384
    k_zero<<<1024, 256>>>((float4*)agg, n * NF / 4);
    k_rel_prop_mma<<<148, 256, RP2_SMEM_BYTES>>>(ee, eff, recv, send, rp_w, rp_b, agg, e);
    k_part_prop_mma<<<148, 256, PP_SMEM_BYTES>>>(pe, agg, pp_w, pp_b, eff, n);

    // decoder
    k_decoder_mma<<<148, 256, DE_SMEM_BYTES>>>(eff, de_w1, de_b1, de_w2, de_b2,
                                               de_w3, de_b3, (float*)d_out, n);
}

// round 17
// speedup vs baseline: 1.0441x; 1.0211x over previous
#include <cuda_runtime.h>
#include <cuda_bf16.h>
#include <cstdint>

// Problem constants (fixed by the dataset)
#define NN 100000
#define EE 500000
#define NF 128
#define ATTR_W 16
#define STATE_W 12
#define REL_W 4
#define PSTEP 2

// Scratch (device globals; no runtime allocation allowed)
__device__ float g_pe [NN * NF];
__device__ float g_pe2[NN * NF];           // pe @ pp_w[0:128]  (fp32 partial)
__device__ float g_ee [EE * NF];
__device__ float g_eff[NN * NF];
__device__ float g_agg[NN * NF];
__device__ float g_attr_r [NN * ATTR_W];   // tf32-pre-rounded inputs
__device__ float g_state_r[NN * STATE_W];
__device__ float g_ra_r   [EE * REL_W];

// ---------------------------------------------------------------------------
// helpers
// ---------------------------------------------------------------------------
__device__ __forceinline__ uint32_t cvt_tf32(float x) {
    uint32_t r;
    asm("cvt.rna.tf32.f32 %0, %1;" : "=r"(r) : "f"(x));
    return r;
}
__device__ __forceinline__ float cvt_tf32f(float x) {
    return __uint_as_float(cvt_tf32(x));
}

__device__ __forceinline__ void mma_tf32(float* c, const uint32_t* a, const uint32_t* b) {
    asm volatile(
        "mma.sync.aligned.m16n8k8.row.col.f32.tf32.tf32.f32 "
        "{%0,%1,%2,%3}, {%4,%5,%6,%7}, {%8,%9}, {%0,%1,%2,%3};"
        : "+f"(c[0]), "+f"(c[1]), "+f"(c[2]), "+f"(c[3])
        : "r"(a[0]), "r"(a[1]), "r"(a[2]), "r"(a[3]), "r"(b[0]), "r"(b[1]));
}

__device__ __forceinline__ void ldsm_x4(uint32_t* r, uint32_t addr) {
    asm volatile("ldmatrix.sync.aligned.m8n8.x4.shared.b16 {%0,%1,%2,%3}, [%4];"
                 : "=r"(r[0]), "=r"(r[1]), "=r"(r[2]), "=r"(r[3]) : "r"(addr));
}
__device__ __forceinline__ void ldsm_x2(uint32_t* r, uint32_t addr) {
    asm volatile("ldmatrix.sync.aligned.m8n8.x2.shared.b16 {%0,%1}, [%2];"
                 : "=r"(r[0]), "=r"(r[1]) : "r"(addr));
}

__device__ __forceinline__ void red2(float* p, float a, float b) {
    asm volatile("red.global.add.v2.f32 [%0], {%1, %2};" :: "l"(p), "f"(a), "f"(b) : "memory");
}

__device__ __forceinline__ uint32_t smem_u32(const void* p) {
    uint32_t a;
    asm("{ .reg .u64 t; cvta.to.shared.u64 t, %1; cvt.u32.u64 %0, t; }" : "=r"(a) : "l"(p));
    return a;
}

// 16-byte async copy, zero-fill when !valid
__device__ __forceinline__ void cp_async16(uint32_t dst, const float* src, bool valid) {
    int sz = valid ? 16 : 0;
    asm volatile("cp.async.ca.shared.global [%0], [%1], 16, %2;"
                 :: "r"(dst), "l"(src), "r"(sz) : "memory");
}
#define CP_COMMIT() asm volatile("cp.async.commit_group;" ::: "memory")
#define CP_WAIT0()  asm volatile("cp.async.wait_group 0;" ::: "memory")

// weight swizzle (k-major, for node_enc): addr = k*128 + (n ^ ((k&3)<<3))
#define WSW(k, n) (((k) << 7) + ((n) ^ (((k) & 3) << 3)))
// transposed weight swizzle, stride S floats: addr = n*S + (k ^ ((n&7)<<2))
#define WTS(nn, k, S) ((nn) * (S) + ((k) ^ (((nn) & 7) << 2)))
// activation swizzle (stride 128): addr = r*128 + (c ^ ((r&7)<<2))
#define ASW(r, c) (((r) << 7) + ((c) ^ (((r) & 7) << 2)))
// chunk swizzle (stride 32): addr = r*32 + (c ^ ((r&7)<<2)), c in 0..31
#define ACSW(r, c) (((r) << 5) + ((c) ^ (((r) & 7) << 2)))

// ---------------------------------------------------------------------------
// zero kernel (float4) and input pre-rounding
// ---------------------------------------------------------------------------
__global__ void k_zero(float4* p, int n4) {
    int i = blockIdx.x * blockDim.x + threadIdx.x;
    int stride = gridDim.x * blockDim.x;
    float4 z = make_float4(0.f, 0.f, 0.f, 0.f);
    for (; i < n4; i += stride) p[i] = z;
}

__global__ void k_round3(const float* __restrict__ a, float* __restrict__ ar, int na,
                         const float* __restrict__ s, float* __restrict__ sr, int ns,
                         const float* __restrict__ r, float* __restrict__ rr, int nr) {
    int i = blockIdx.x * blockDim.x + threadIdx.x;
    int stride = gridDim.x * blockDim.x;
    for (int j = i; j < na; j += stride) ar[j] = cvt_tf32f(a[j]);
    for (int j = i; j < ns; j += stride) sr[j] = cvt_tf32f(s[j]);
    for (int j = i; j < nr; j += stride) rr[j] = cvt_tf32f(r[j]);
}

// ---------------------------------------------------------------------------
// Node encoder via mma.sync tf32 (round-14/15/16 passing, unchanged)
// ---------------------------------------------------------------------------
#define NE_OFF_B1   0
#define NE_OFF_B2   512
#define NE_OFF_IN   1024
#define NE_OFF_W1   (NE_OFF_IN + 16384)
#define NE_OFF_W2   (NE_OFF_W1 + 16384)
#define NE_OFF_ACT  (NE_OFF_W2 + 65536)
#define NE_SMEM_BYTES (NE_OFF_ACT + 65536)

__global__ __launch_bounds__(256, 1) void k_node_enc_mma(
    const float* __restrict__ attr, const float* __restrict__ state,
    const float* __restrict__ w1, const float* __restrict__ b1,
    const float* __restrict__ w2, const float* __restrict__ b2,
    float* __restrict__ pe, int n)
{
    extern __shared__ char smem[];
    float*    s_b1 = (float*)   (smem + NE_OFF_B1);
    float*    s_b2 = (float*)   (smem + NE_OFF_B2);
    uint32_t* INs  = (uint32_t*)(smem + NE_OFF_IN);
    uint32_t* W1s  = (uint32_t*)(smem + NE_OFF_W1);
    uint32_t* W2s  = (uint32_t*)(smem + NE_OFF_W2);
    uint32_t* As   = (uint32_t*)(smem + NE_OFF_ACT);

    const int tid = threadIdx.x;
    const int wid = tid >> 5;
    const int lane = tid & 31;
    const int grp = lane >> 2;
    const int tg  = lane & 3;
    const int wm  = wid & 3;
    const int wn  = wid >> 2;

    for (int idx = tid; idx < 32 * 128; idx += 256) {
        int k = idx >> 7, nn = idx & 127;
        float v = (k < 28) ? w1[k * NF + nn] : 0.f;
        W1s[WSW(k, nn)] = cvt_tf32(v);
    }
    for (int idx = tid; idx < 128 * 128; idx += 256) {
        int k = idx >> 7, nn = idx & 127;
        W2s[WSW(k, nn)] = cvt_tf32(w2[k * NF + nn]);
    }
    if (tid < 128) { s_b1[tid] = b1[tid]; s_b2[tid] = b2[tid]; }
    __syncthreads();

    const int ntiles = (n + 127) >> 7;
    const int r_st   = tid >> 1;
    const int half   = tid & 1;

    float acc[2][8][4];

    for (int tile = blockIdx.x; tile < ntiles; tile += gridDim.x) {
        const int n0 = tile << 7;
        const int row = n0 + r_st;
        const bool rv = (row < n);

        if (half == 0) {
#pragma unroll
            for (int q = 0; q < 4; q++) {
                float4 v = rv ? *(const float4*)(attr + (size_t)row * ATTR_W + q * 4)
                              : make_float4(0.f, 0.f, 0.f, 0.f);
                uint4 u = { cvt_tf32(v.x), cvt_tf32(v.y), cvt_tf32(v.z), cvt_tf32(v.w) };
                *(uint4*)(INs + ACSW(r_st, q * 4)) = u;
            }
        } else {
#pragma unroll
            for (int q = 0; q < 3; q++) {
                float4 v = rv ? *(const float4*)(state + (size_t)row * STATE_W + q * 4)
                              : make_float4(0.f, 0.f, 0.f, 0.f);
                uint4 u = { cvt_tf32(v.x), cvt_tf32(v.y), cvt_tf32(v.z), cvt_tf32(v.w) };
                *(uint4*)(INs + ACSW(r_st, 16 + q * 4)) = u;
            }
            uint4 z = { 0u, 0u, 0u, 0u };
            *(uint4*)(INs + ACSW(r_st, 28)) = z;
        }
        __syncthreads();

        // layer 1 (k=32)
#pragma unroll
        for (int mt = 0; mt < 2; mt++)
#pragma unroll
            for (int nt = 0; nt < 8; nt++)
#pragma unroll
                for (int i = 0; i < 4; i++) acc[mt][nt][i] = 0.f;
#pragma unroll
        for (int s = 0; s < 4; s++) {
            const int kk = s * 8;
            uint32_t bf[8][2];
#pragma unroll
            for (int nt = 0; nt < 8; nt++) {
                int n_sw = (wn * 64 + nt * 8 + grp) ^ (tg << 3);
                bf[nt][0] = W1s[((kk + tg) << 7) + n_sw];
                bf[nt][1] = W1s[((kk + tg + 4) << 7) + n_sw];
            }
#pragma unroll
            for (int mt = 0; mt < 2; mt++) {
                int rb = wm * 32 + mt * 16;
                uint32_t af[4];
                af[0] = INs[ACSW(rb + grp,     kk + tg)];
                af[1] = INs[ACSW(rb + grp + 8, kk + tg)];
                af[2] = INs[ACSW(rb + grp,     kk + tg + 4)];
                af[3] = INs[ACSW(rb + grp + 8, kk + tg + 4)];
#pragma unroll
                for (int nt = 0; nt < 8; nt++)
                    mma_tf32(acc[mt][nt], af, bf[nt]);
            }
        }

        // h1 -> As
#pragma unroll
        for (int mt = 0; mt < 2; mt++) {
            int r_lo = wm * 32 + mt * 16 + grp;
            int r_hi = r_lo + 8;
#pragma unroll
            for (int nt = 0; nt < 8; nt++) {
                int col = wn * 64 + nt * 8 + tg * 2;
                float b0 = s_b1[col], b1v = s_b1[col + 1];
                uint2 lo = { cvt_tf32(fmaxf(acc[mt][nt][0] + b0, 0.f)),
                             cvt_tf32(fmaxf(acc[mt][nt][1] + b1v, 0.f)) };
                uint2 hi = { cvt_tf32(fmaxf(acc[mt][nt][2] + b0, 0.f)),
                             cvt_tf32(fmaxf(acc[mt][nt][3] + b1v, 0.f)) };
                *(uint2*)(As + ASW(r_lo, col)) = lo;
                *(uint2*)(As + ASW(r_hi, col)) = hi;
            }
        }
        __syncthreads();

        // layer 2 (k=128)
#pragma unroll
        for (int mt = 0; mt < 2; mt++)
#pragma unroll
            for (int nt = 0; nt < 8; nt++)
#pragma unroll
                for (int i = 0; i < 4; i++) acc[mt][nt][i] = 0.f;
#pragma unroll
        for (int s = 0; s < 16; s++) {
            const int kk = s * 8;
            uint32_t bf[8][2];
#pragma unroll
            for (int nt = 0; nt < 8; nt++) {
                int n_sw = (wn * 64 + nt * 8 + grp) ^ (tg << 3);
                bf[nt][0] = W2s[((kk + tg) << 7) + n_sw];
                bf[nt][1] = W2s[((kk + tg + 4) << 7) + n_sw];
            }
#pragma unroll
            for (int mt = 0; mt < 2; mt++) {
                int rb = wm * 32 + mt * 16;
                uint32_t af[4];
                af[0] = As[ASW(rb + grp,     kk + tg)];
                af[1] = As[ASW(rb + grp + 8, kk + tg)];
                af[2] = As[ASW(rb + grp,     kk + tg + 4)];
                af[3] = As[ASW(rb + grp + 8, kk + tg + 4)];
#pragma unroll
                for (int nt = 0; nt < 8; nt++)
                    mma_tf32(acc[mt][nt], af, bf[nt]);
            }
        }
        __syncthreads();

        // store pe (tf32-rounded)
#pragma unroll
        for (int mt = 0; mt < 2; mt++) {
            int r_lo = wm * 32 + mt * 16 + grp;
            int r_hi = r_lo + 8;
            bool v_lo = (n0 + r_lo) < n;
            bool v_hi = (n0 + r_hi) < n;
#pragma unroll
            for (int nt = 0; nt < 8; nt++) {
                int col = wn * 64 + nt * 8 + tg * 2;
                float b0 = s_b2[col], b1v = s_b2[col + 1];
                if (v_lo) {
                    float2 v = { cvt_tf32f(fmaxf(acc[mt][nt][0] + b0, 0.f)),
                                 cvt_tf32f(fmaxf(acc[mt][nt][1] + b1v, 0.f)) };
                    *(float2*)(pe + (size_t)(n0 + r_lo) * NF + col) = v;
                }
                if (v_hi) {
                    float2 v = { cvt_tf32f(fmaxf(acc[mt][nt][2] + b0, 0.f)),
                                 cvt_tf32f(fmaxf(acc[mt][nt][3] + b1v, 0.f)) };
                    *(float2*)(pe + (size_t)(n0 + r_hi) * NF + col) = v;
                }
            }
        }
    }
}

// ---------------------------------------------------------------------------
// Edge encoder via mma.sync tf32 (round-15/16 passing) — ldmatrix loads
// ---------------------------------------------------------------------------
#define EE_OFF_RECV 0
#define EE_OFF_SEND 512
#define EE_OFF_B1   1024
#define EE_OFF_B2   1536
#define EE_OFF_B3   2048
#define EE_OFF_W1   2560
#define EE_OFF_W2   (EE_OFF_W1 + 32768)
#define EE_OFF_W3   (EE_OFF_W2 + 65536)
#define EE_OFF_ACT  (EE_OFF_W3 + 65536)
#define EE_SMEM_BYTES (EE_OFF_ACT + 65536)

__global__ __launch_bounds__(256, 1) void k_edge_enc_mma(
    const float* __restrict__ attr, const float* __restrict__ state,
    const float* __restrict__ Ra,
    const int* __restrict__ recv, const int* __restrict__ send,
    const float* __restrict__ w1, const float* __restrict__ b1,
    const float* __restrict__ w2, const float* __restrict__ b2,
    const float* __restrict__ w3, const float* __restrict__ b3,
    float* __restrict__ ee, int e_cnt)
{
    extern __shared__ char smem[];
    int*      s_recv = (int*)     (smem + EE_OFF_RECV);
    int*      s_send = (int*)     (smem + EE_OFF_SEND);
    float*    s_b1   = (float*)   (smem + EE_OFF_B1);
    float*    s_b2   = (float*)   (smem + EE_OFF_B2);
    float*    s_b3   = (float*)   (smem + EE_OFF_B3);
    uint32_t* W1s    = (uint32_t*)(smem + EE_OFF_W1);
    uint32_t* W2s    = (uint32_t*)(smem + EE_OFF_W2);
    uint32_t* W3s    = (uint32_t*)(smem + EE_OFF_W3);
    const uint32_t sb = smem_u32(smem);
    const uint32_t actb = sb + EE_OFF_ACT;
    const uint32_t w1b  = sb + EE_OFF_W1;
    const uint32_t w2b  = sb + EE_OFF_W2;
    const uint32_t w3b  = sb + EE_OFF_W3;

    const int tid = threadIdx.x;
    const int wid = tid >> 5;
    const int lane = tid & 31;
    const int grp = lane >> 2;
    const int tg  = lane & 3;
    const int wm  = wid & 3;
    const int wn  = wid >> 2;
    const int l8  = lane & 7;
    const int lj1 = (lane >> 3) & 1;
    const int lj2 = lane >> 4;

    for (int idx = tid; idx < 64 * 128; idx += 256) {
        int k = idx >> 7, n = idx & 127;
        float v = (k < 60) ? w1[k * NF + n] : 0.f;
        W1s[WTS(n, k, 64)] = cvt_tf32(v);
    }
    for (int idx = tid; idx < 128 * 128; idx += 256) {
        int k = idx >> 7, n = idx & 127;
        W2s[WTS(n, k, 128)] = cvt_tf32(w2[k * NF + n]);
        W3s[WTS(n, k, 128)] = cvt_tf32(w3[k * NF + n]);
    }
    if (tid < 128) { s_b1[tid] = b1[tid]; s_b2[tid] = b2[tid]; s_b3[tid] = b3[tid]; }

    const int ntiles = (e_cnt + 127) >> 7;
    const int r_st   = tid >> 1;
    const int half   = tid & 1;

    float acc[2][8][4];

    __syncthreads();

    for (int tile = blockIdx.x; tile < ntiles; tile += gridDim.x) {
        const int e0 = tile << 7;
        if (tid < 128) {
            int e = e0 + tid;
            s_recv[tid] = (e < e_cnt) ? recv[e] : 0;
            s_send[tid] = (e < e_cnt) ? send[e] : 0;
        }
        __syncthreads();

        // gather [128 x 64] via cp.async (sources pre-rounded tf32)
        {
            int rv = s_recv[r_st], sv = s_send[r_st];
            int e  = e0 + r_st;
            bool ev = (e < e_cnt);
            if (half == 0) {
                const float* a_rv = attr + (size_t)rv * ATTR_W;
                const float* a_sv = attr + (size_t)sv * ATTR_W;
#pragma unroll
                for (int q = 0; q < 4; q++)
                    cp_async16(actb + 4 * ASW(r_st, q * 4), a_rv + q * 4, true);
#pragma unroll
                for (int q = 0; q < 4; q++)
                    cp_async16(actb + 4 * ASW(r_st, 16 + q * 4), a_sv + q * 4, true);
            } else {
                const float* s_rv = state + (size_t)rv * STATE_W;
                const float* s_sv = state + (size_t)sv * STATE_W;
#pragma unroll
                for (int q = 0; q < 3; q++)
                    cp_async16(actb + 4 * ASW(r_st, 32 + q * 4), s_rv + q * 4, true);
#pragma unroll
                for (int q = 0; q < 3; q++)
                    cp_async16(actb + 4 * ASW(r_st, 44 + q * 4), s_sv + q * 4, true);
                cp_async16(actb + 4 * ASW(r_st, 56), Ra + (size_t)(ev ? e : 0) * REL_W, ev);
                cp_async16(actb + 4 * ASW(r_st, 60), Ra, false);  // zfill pad
            }
            CP_COMMIT();
            CP_WAIT0();
        }
        __syncthreads();

        // layer 1 (k=64, W1 transposed stride 64)
#pragma unroll
        for (int mt = 0; mt < 2; mt++)
#pragma unroll
            for (int nt = 0; nt < 8; nt++)
#pragma unroll
                for (int i = 0; i < 4; i++) acc[mt][nt][i] = 0.f;
#pragma unroll
        for (int s = 0; s < 8; s++) {
            const int kk = s * 8;
            const int bk = (kk + lj1 * 4) ^ (l8 << 2);
            uint32_t bf[8][2];
#pragma unroll
            for (int nt = 0; nt < 8; nt++) {
                int nrow = wn * 64 + nt * 8 + l8;
                ldsm_x2(bf[nt], w1b + 4 * (nrow * 64 + bk));
            }
#pragma unroll
            for (int mt = 0; mt < 2; mt++) {
                int arow = wm * 32 + mt * 16 + l8 + lj1 * 8;
                int acol = (kk + lj2 * 4) ^ ((arow & 7) << 2);
                uint32_t af[4];
                ldsm_x4(af, actb + 4 * (arow * 128 + acol));
#pragma unroll
                for (int nt = 0; nt < 8; nt++)
                    mma_tf32(acc[mt][nt], af, bf[nt]);
            }
        }
        __syncthreads();

#pragma unroll
        for (int mt = 0; mt < 2; mt++) {
            int r_lo = wm * 32 + mt * 16 + grp;
            int r_hi = r_lo + 8;
#pragma unroll
            for (int nt = 0; nt < 8; nt++) {
                int col = wn * 64 + nt * 8 + tg * 2;
                float b0 = s_b1[col], b1v = s_b1[col + 1];
                uint2 lo = { cvt_tf32(fmaxf(acc[mt][nt][0] + b0, 0.f)),
                             cvt_tf32(fmaxf(acc[mt][nt][1] + b1v, 0.f)) };
                uint2 hi = { cvt_tf32(fmaxf(acc[mt][nt][2] + b0, 0.f)),
                             cvt_tf32(fmaxf(acc[mt][nt][3] + b1v, 0.f)) };
                *(uint2*)((uint32_t*)(smem + EE_OFF_ACT) + ASW(r_lo, col)) = lo;
                *(uint2*)((uint32_t*)(smem + EE_OFF_ACT) + ASW(r_hi, col)) = hi;
            }
        }
        __syncthreads();

        // layer 2 (k=128, W2 transposed stride 128)
#pragma unroll
        for (int mt = 0; mt < 2; mt++)
#pragma unroll
            for (int nt = 0; nt < 8; nt++)
#pragma unroll
                for (int i = 0; i < 4; i++) acc[mt][nt][i] = 0.f;
#pragma unroll
        for (int s = 0; s < 16; s++) {
            const int kk = s * 8;
            const int bk = (kk + lj1 * 4) ^ (l8 << 2);
            uint32_t bf[8][2];
#pragma unroll
            for (int nt = 0; nt < 8; nt++) {
                int nrow = wn * 64 + nt * 8 + l8;
                ldsm_x2(bf[nt], w2b + 4 * (nrow * 128 + bk));
            }
#pragma unroll
            for (int mt = 0; mt < 2; mt++) {
                int arow = wm * 32 + mt * 16 + l8 + lj1 * 8;
                int acol = (kk + lj2 * 4) ^ ((arow & 7) << 2);
                uint32_t af[4];
                ldsm_x4(af, actb + 4 * (arow * 128 + acol));
#pragma unroll
                for (int nt = 0; nt < 8; nt++)
                    mma_tf32(acc[mt][nt], af, bf[nt]);
            }
        }
        __syncthreads();

#pragma unroll
        for (int mt = 0; mt < 2; mt++) {
            int r_lo = wm * 32 + mt * 16 + grp;
            int r_hi = r_lo + 8;
#pragma unroll
            for (int nt = 0; nt < 8; nt++) {
                int col = wn * 64 + nt * 8 + tg * 2;
                float b0 = s_b2[col], b1v = s_b2[col + 1];
                uint2 lo = { cvt_tf32(fmaxf(acc[mt][nt][0] + b0, 0.f)),
                             cvt_tf32(fmaxf(acc[mt][nt][1] + b1v, 0.f)) };
                uint2 hi = { cvt_tf32(fmaxf(acc[mt][nt][2] + b0, 0.f)),
                             cvt_tf32(fmaxf(acc[mt][nt][3] + b1v, 0.f)) };
                *(uint2*)((uint32_t*)(smem + EE_OFF_ACT) + ASW(r_lo, col)) = lo;
                *(uint2*)((uint32_t*)(smem + EE_OFF_ACT) + ASW(r_hi, col)) = hi;
            }
        }
        __syncthreads();

        // layer 3 (k=128, W3 transposed) -> ee
#pragma unroll
        for (int mt = 0; mt < 2; mt++)
#pragma unroll
            for (int nt = 0; nt < 8; nt++)
#pragma unroll
                for (int i = 0; i < 4; i++) acc[mt][nt][i] = 0.f;
#pragma unroll
        for (int s = 0; s < 16; s++) {
            const int kk = s * 8;
            const int bk = (kk + lj1 * 4) ^ (l8 << 2);
            uint32_t bf[8][2];
#pragma unroll
            for (int nt = 0; nt < 8; nt++) {
                int nrow = wn * 64 + nt * 8 + l8;
                ldsm_x2(bf[nt], w3b + 4 * (nrow * 128 + bk));
            }
#pragma unroll
            for (int mt = 0; mt < 2; mt++) {
                int arow = wm * 32 + mt * 16 + l8 + lj1 * 8;
                int acol = (kk + lj2 * 4) ^ ((arow & 7) << 2);
                uint32_t af[4];
                ldsm_x4(af, actb + 4 * (arow * 128 + acol));
#pragma unroll
                for (int nt = 0; nt < 8; nt++)
                    mma_tf32(acc[mt][nt], af, bf[nt]);
            }
        }
        __syncthreads();

        // epilogue: ee = tf32(relu(acc + b3))
#pragma unroll
        for (int mt = 0; mt < 2; mt++) {
            int r_lo = wm * 32 + mt * 16 + grp;
            int r_hi = r_lo + 8;
            bool v_lo = (e0 + r_lo) < e_cnt;
            bool v_hi = (e0 + r_hi) < e_cnt;
#pragma unroll
            for (int nt = 0; nt < 8; nt++) {
                int col = wn * 64 + nt * 8 + tg * 2;
                float b0 = s_b3[col], b1v = s_b3[col + 1];
                if (v_lo) {
                    float2 v = { cvt_tf32f(fmaxf(acc[mt][nt][0] + b0, 0.f)),
                                 cvt_tf32f(fmaxf(acc[mt][nt][1] + b1v, 0.f)) };
                    *(float2*)(ee + (size_t)(e0 + r_lo) * NF + col) = v;
                }
                if (v_hi) {
                    float2 v = { cvt_tf32f(fmaxf(acc[mt][nt][2] + b0, 0.f)),
                                 cvt_tf32f(fmaxf(acc[mt][nt][3] + b1v, 0.f)) };
                    *(float2*)(ee + (size_t)(e0 + r_hi) * NF + col) = v;
                }
            }
        }
    }
}

// ---------------------------------------------------------------------------
// Relation propagator (nch=12 path, round-14/15/16 passing)
// ---------------------------------------------------------------------------
#define RP2_OFF_RECV 0
#define RP2_OFF_SEND 512
#define RP2_OFF_BIAS 1024
#define RP2_OFF_A0   1536
#define RP2_OFF_A1   (RP2_OFF_A0 + 16384)
#define RP2_OFF_B    (RP2_OFF_A1 + 16384)
#define RP2_SMEM_BYTES (RP2_OFF_B + 384 * 128 * 4)

__global__ __launch_bounds__(256, 1) void k_rel_prop_mma(
    const float* __restrict__ ee, const float* __restrict__ eff,
    const int* __restrict__ recv, const int* __restrict__ send,
    const float* __restrict__ w, const float* __restrict__ b,
    float* __restrict__ agg, int e_cnt)
{
    extern __shared__ char smem[];
    int*      s_recv = (int*)     (smem + RP2_OFF_RECV);
    int*      s_send = (int*)     (smem + RP2_OFF_SEND);
    float*    s_bias = (float*)   (smem + RP2_OFF_BIAS);
    uint32_t* Bs     = (uint32_t*)(smem + RP2_OFF_B);     // transposed [128][384]
    const uint32_t sb = smem_u32(smem);
    const uint32_t a0b = sb + RP2_OFF_A0;
    const uint32_t a1b = sb + RP2_OFF_A1;
    const uint32_t btb = sb + RP2_OFF_B;

    const int tid = threadIdx.x;
    const int wid = tid >> 5;
    const int lane = tid & 31;
    const int grp = lane >> 2;
    const int tg  = lane & 3;
    const int wm  = wid & 3;
    const int wn  = wid >> 2;
    const int l8  = lane & 7;
    const int lj1 = (lane >> 3) & 1;
    const int lj2 = lane >> 4;
    const int bxor = l8 << 2;

    for (int idx = tid; idx < 12 * 32 * 128; idx += 256) {
        int k = idx >> 7, n = idx & 127;
        Bs[WTS(n, k, 384)] = cvt_tf32(w[k * NF + n]);
    }
    if (tid < 128) s_bias[tid] = b[tid];
    __syncthreads();

    const int ntiles = (e_cnt + 127) >> 7;
    const int r_st   = tid >> 1;
    const int half   = tid & 1;

    for (int tile = blockIdx.x; tile < ntiles; tile += gridDim.x) {
        const int e0 = tile << 7;

        {
            int e = e0 + r_st;
            bool valid = (e < e_cnt);
            const float* src = ee + (size_t)(valid ? e : 0) * NF + half * 16;
#pragma unroll
            for (int q = 0; q < 4; q++)
                cp_async16(a0b + 4 * ACSW(r_st, half * 16 + q * 4), src + q * 4, valid);
            CP_COMMIT();
        }

        if (tid < 128) {
            int e = e0 + tid;
            s_recv[tid] = (e < e_cnt) ? recv[e] : 0;
            s_send[tid] = (e < e_cnt) ? send[e] : 0;
        }

        float acc[2][8][4];
#pragma unroll
        for (int mt = 0; mt < 2; mt++)
#pragma unroll
            for (int nt = 0; nt < 8; nt++)
#pragma unroll
                for (int i = 0; i < 4; i++) acc[mt][nt][i] = 0.f;

        __syncthreads();

        for (int c = 0; c < 12; c++) {
            CP_WAIT0();
            __syncthreads();

            if (c + 1 < 12) {
                int cn = c + 1;
                const float* src;
                bool valid = true;
                if (cn < 4) {
                    int e = e0 + r_st;
                    valid = (e < e_cnt);
                    src = ee + (size_t)(valid ? e : 0) * NF + cn * 32;
                } else if (cn < 8) {
                    src = eff + (size_t)s_recv[r_st] * NF + (cn - 4) * 32;
                } else {
                    src = eff + (size_t)s_send[r_st] * NF + (cn - 8) * 32;
                }
                uint32_t abase = (cn & 1) ? a1b : a0b;
#pragma unroll
                for (int q = 0; q < 4; q++)
                    cp_async16(abase + 4 * ACSW(r_st, half * 16 + q * 4),
                               src + half * 16 + q * 4, valid);
                CP_COMMIT();
            }

            const uint32_t abufb = (c & 1) ? a1b : a0b;
#pragma unroll
            for (int s = 0; s < 4; s++) {
                const int ac = s * 8;
                const int kk = c * 32 + ac;
                const int bk = (kk + lj1 * 4) ^ bxor;
                uint32_t bf[8][2];
#pragma unroll
                for (int nt = 0; nt < 8; nt++) {
                    int nrow = wn * 64 + nt * 8 + l8;
                    ldsm_x2(bf[nt], btb + 4 * (nrow * 384 + bk));
                }
#pragma unroll
                for (int mt = 0; mt < 2; mt++) {
                    int arow = wm * 32 + mt * 16 + l8 + lj1 * 8;
                    int acol = (ac + lj2 * 4) ^ ((arow & 7) << 2);
                    uint32_t af[4];
                    ldsm_x4(af, abufb + 4 * (arow * 32 + acol));
#pragma unroll
                    for (int nt = 0; nt < 8; nt++)
                        mma_tf32(acc[mt][nt], af, bf[nt]);
                }
            }
        }

        // epilogue: bias + relu + red.v2 scatter
#pragma unroll
        for (int mt = 0; mt < 2; mt++) {
            int r_lo = wm * 32 + mt * 16 + grp;
            int r_hi = r_lo + 8;
            bool v_lo = (e0 + r_lo) < e_cnt;
            bool v_hi = (e0 + r_hi) < e_cnt;
            int d_lo = s_recv[r_lo];
            int d_hi = s_recv[r_hi];
#pragma unroll
            for (int nt = 0; nt < 8; nt++) {
                int col = wn * 64 + nt * 8 + tg * 2;
                float b0 = s_bias[col], b1 = s_bias[col + 1];
                if (v_lo)
                    red2(&agg[(size_t)d_lo * NF + col],
                         fmaxf(acc[mt][nt][0] + b0, 0.f),
                         fmaxf(acc[mt][nt][1] + b1, 0.f));
                if (v_hi)
                    red2(&agg[(size_t)d_hi * NF + col],
                         fmaxf(acc[mt][nt][2] + b0, 0.f),
                         fmaxf(acc[mt][nt][3] + b1, 0.f));
            }
        }
        __syncthreads();
    }
}

// ---------------------------------------------------------------------------
// Relation propagator ps=0 (nch=4, round-16 passing): 2 CTAs/SM
// ---------------------------------------------------------------------------
#define RP4_OFF_B    RP2_OFF_B
#define RP4_SMEM_BYTES (RP4_OFF_B + 128 * 128 * 4)

__global__ __launch_bounds__(256, 2) void k_rel_prop_mma4(
    const float* __restrict__ ee,
    const int* __restrict__ recv,
    const float* __restrict__ w, const float* __restrict__ b,
    float* __restrict__ agg, int e_cnt)
{
    extern __shared__ char smem[];
    int*      s_recv = (int*)     (smem + RP2_OFF_RECV);
    float*    s_bias = (float*)   (smem + RP2_OFF_BIAS);
    uint32_t* Bs     = (uint32_t*)(smem + RP4_OFF_B);     // transposed [128][128]
    const uint32_t sb = smem_u32(smem);
    const uint32_t a0b = sb + RP2_OFF_A0;
    const uint32_t a1b = sb + RP2_OFF_A1;
    const uint32_t btb = sb + RP4_OFF_B;

    const int tid = threadIdx.x;
    const int wid = tid >> 5;
    const int lane = tid & 31;
    const int grp = lane >> 2;
    const int tg  = lane & 3;
    const int wm  = wid & 3;
    const int wn  = wid >> 2;
    const int l8  = lane & 7;
    const int lj1 = (lane >> 3) & 1;
    const int lj2 = lane >> 4;
    const int bxor = l8 << 2;

    for (int idx = tid; idx < 128 * 128; idx += 256) {
        int k = idx >> 7, n = idx & 127;
        Bs[WTS(n, k, 128)] = cvt_tf32(w[k * NF + n]);
    }
    if (tid < 128) s_bias[tid] = b[tid];
    __syncthreads();

    const int ntiles = (e_cnt + 127) >> 7;
    const int r_st   = tid >> 1;
    const int half   = tid & 1;

    for (int tile = blockIdx.x; tile < ntiles; tile += gridDim.x) {
        const int e0 = tile << 7;

        {
            int e = e0 + r_st;
            bool valid = (e < e_cnt);
            const float* src = ee + (size_t)(valid ? e : 0) * NF + half * 16;
#pragma unroll
            for (int q = 0; q < 4; q++)
                cp_async16(a0b + 4 * ACSW(r_st, half * 16 + q * 4), src + q * 4, valid);
            CP_COMMIT();
        }

        if (tid < 128) {
            int e = e0 + tid;
            s_recv[tid] = (e < e_cnt) ? recv[e] : 0;
        }

        float acc[2][8][4];
#pragma unroll
        for (int mt = 0; mt < 2; mt++)
#pragma unroll
            for (int nt = 0; nt < 8; nt++)
#pragma unroll
                for (int i = 0; i < 4; i++) acc[mt][nt][i] = 0.f;

        __syncthreads();

#pragma unroll 1
        for (int c = 0; c < 4; c++) {
            CP_WAIT0();
            __syncthreads();

            if (c + 1 < 4) {
                int cn = c + 1;
                int e = e0 + r_st;
                bool valid = (e < e_cnt);
                const float* src = ee + (size_t)(valid ? e : 0) * NF + cn * 32;
                uint32_t abase = (cn & 1) ? a1b : a0b;
#pragma unroll
                for (int q = 0; q < 4; q++)
                    cp_async16(abase + 4 * ACSW(r_st, half * 16 + q * 4),
                               src + half * 16 + q * 4, valid);
                CP_COMMIT();
            }

            const uint32_t abufb = (c & 1) ? a1b : a0b;
#pragma unroll
            for (int s = 0; s < 4; s++) {
                const int ac = s * 8;
                const int kk = c * 32 + ac;
                const int bk = (kk + lj1 * 4) ^ bxor;
                uint32_t bf[8][2];
#pragma unroll
                for (int nt = 0; nt < 8; nt++) {
                    int nrow = wn * 64 + nt * 8 + l8;
                    ldsm_x2(bf[nt], btb + 4 * (nrow * 128 + bk));
                }
#pragma unroll
                for (int mt = 0; mt < 2; mt++) {
                    int arow = wm * 32 + mt * 16 + l8 + lj1 * 8;
                    int acol = (ac + lj2 * 4) ^ ((arow & 7) << 2);
                    uint32_t af[4];
                    ldsm_x4(af, abufb + 4 * (arow * 32 + acol));
#pragma unroll
                    for (int nt = 0; nt < 8; nt++)
                        mma_tf32(acc[mt][nt], af, bf[nt]);
                }
            }
        }

        // epilogue: bias + relu + red.v2 scatter
#pragma unroll
        for (int mt = 0; mt < 2; mt++) {
            int r_lo = wm * 32 + mt * 16 + grp;
            int r_hi = r_lo + 8;
            bool v_lo = (e0 + r_lo) < e_cnt;
            bool v_hi = (e0 + r_hi) < e_cnt;
            int d_lo = s_recv[r_lo];
            int d_hi = s_recv[r_hi];
#pragma unroll
            for (int nt = 0; nt < 8; nt++) {
                int col = wn * 64 + nt * 8 + tg * 2;
                float b0 = s_bias[col], b1 = s_bias[col + 1];
                if (v_lo)
                    red2(&agg[(size_t)d_lo * NF + col],
                         fmaxf(acc[mt][nt][0] + b0, 0.f),
                         fmaxf(acc[mt][nt][1] + b1, 0.f));
                if (v_hi)
                    red2(&agg[(size_t)d_hi * NF + col],
                         fmaxf(acc[mt][nt][2] + b0, 0.f),
                         fmaxf(acc[mt][nt][3] + b1, 0.f));
            }
        }
        __syncthreads();
    }
}

// ---------------------------------------------------------------------------
// pe2 = pe @ pp_w[0:128]  (fp32 partial, no bias/relu). 2 CTAs/SM, K=128.
// Shared layout for the K=128 kernels:
// ---------------------------------------------------------------------------
#define P2_OFF_BIAS 0
#define P2_OFF_A0   512
#define P2_OFF_A1   (P2_OFF_A0 + 16384)
#define P2_OFF_B    (P2_OFF_A1 + 16384)
#define P2_SMEM_BYTES (P2_OFF_B + 128 * 128 * 4)   // 98816 -> 2 CTAs/SM

__global__ __launch_bounds__(256, 2) void k_pe2_mma(
    const float* __restrict__ pe, const float* __restrict__ w,
    float* __restrict__ pe2, int n)
{
    extern __shared__ char smem[];
    uint32_t* Bs = (uint32_t*)(smem + P2_OFF_B);   // transposed [128 n][128 k]
    const uint32_t sb = smem_u32(smem);
    const uint32_t a0b = sb + P2_OFF_A0;
    const uint32_t a1b = sb + P2_OFF_A1;
    const uint32_t btb = sb + P2_OFF_B;

    const int tid = threadIdx.x;
    const int wid = tid >> 5;
    const int lane = tid & 31;
    const int grp = lane >> 2;
    const int tg  = lane & 3;
    const int wm  = wid & 3;
    const int wn  = wid >> 2;
    const int l8  = lane & 7;
    const int lj1 = (lane >> 3) & 1;
    const int lj2 = lane >> 4;
    const int bxor = l8 << 2;

    for (int idx = tid; idx < 128 * 128; idx += 256) {
        int k = idx >> 7, nn = idx & 127;
        Bs[WTS(nn, k, 128)] = cvt_tf32(w[k * NF + nn]);
    }
    __syncthreads();

    const int ntiles = (n + 127) >> 7;
    const int r_st   = tid >> 1;
    const int half   = tid & 1;

    for (int tile = blockIdx.x; tile < ntiles; tile += gridDim.x) {
        const int n0 = tile << 7;
        const int row = n0 + r_st;
        const bool rv = (row < n);
        const size_t rowc = (size_t)(rv ? row : 0);

        {
            const float* src = pe + rowc * NF + half * 16;
#pragma unroll
            for (int q = 0; q < 4; q++)
                cp_async16(a0b + 4 * ACSW(r_st, half * 16 + q * 4), src + q * 4, rv);
            CP_COMMIT();
        }

        float acc[2][8][4];
#pragma unroll
        for (int mt = 0; mt < 2; mt++)
#pragma unroll
            for (int nt = 0; nt < 8; nt++)
#pragma unroll
                for (int i = 0; i < 4; i++) acc[mt][nt][i] = 0.f;

#pragma unroll 1
        for (int c = 0; c < 4; c++) {
            CP_WAIT0();
            __syncthreads();

            if (c + 1 < 4) {
                int cn = c + 1;
                const float* src = pe + rowc * NF + cn * 32;
                uint32_t abase = (cn & 1) ? a1b : a0b;
#pragma unroll
                for (int q = 0; q < 4; q++)
                    cp_async16(abase + 4 * ACSW(r_st, half * 16 + q * 4),
                               src + half * 16 + q * 4, rv);
                CP_COMMIT();
            }

            const uint32_t abufb = (c & 1) ? a1b : a0b;
#pragma unroll
            for (int s = 0; s < 4; s++) {
                const int ac = s * 8;
                const int kk = c * 32 + ac;
                const int bk = (kk + lj1 * 4) ^ bxor;
                uint32_t bf[8][2];
#pragma unroll
                for (int nt = 0; nt < 8; nt++) {
                    int nrow = wn * 64 + nt * 8 + l8;
                    ldsm_x2(bf[nt], btb + 4 * (nrow * 128 + bk));
                }
#pragma unroll
                for (int mt = 0; mt < 2; mt++) {
                    int arow = wm * 32 + mt * 16 + l8 + lj1 * 8;
                    int acol = (ac + lj2 * 4) ^ ((arow & 7) << 2);
                    uint32_t af[4];
                    ldsm_x4(af, abufb + 4 * (arow * 32 + acol));
#pragma unroll
                    for (int nt = 0; nt < 8; nt++)
                        mma_tf32(acc[mt][nt], af, bf[nt]);
                }
            }
        }

        // epilogue: store raw fp32 partial
#pragma unroll
        for (int mt = 0; mt < 2; mt++) {
            int r_lo = wm * 32 + mt * 16 + grp;
            int r_hi = r_lo + 8;
            bool v_lo = (n0 + r_lo) < n;
            bool v_hi = (n0 + r_hi) < n;
#pragma unroll
            for (int nt = 0; nt < 8; nt++) {
                int col = wn * 64 + nt * 8 + tg * 2;
                if (v_lo) {
                    float2 v = { acc[mt][nt][0], acc[mt][nt][1] };
                    *(float2*)(pe2 + (size_t)(n0 + r_lo) * NF + col) = v;
                }
                if (v_hi) {
                    float2 v = { acc[mt][nt][2], acc[mt][nt][3] };
                    *(float2*)(pe2 + (size_t)(n0 + r_hi) * NF + col) = v;
                }
            }
        }
        __syncthreads();
    }
}

// ---------------------------------------------------------------------------
// Particle propagator v4: eff = tf32(relu(pe2 + agg @ pp_w[128:256] + b))
// K=128 only -> B = 64 KB -> 2 CTAs/SM
// ---------------------------------------------------------------------------
__global__ __launch_bounds__(256, 2) void k_part_prop2_mma(
    const float* __restrict__ agg, const float* __restrict__ pe2,
    const float* __restrict__ w2half,   // pp_w + 128*NF
    const float* __restrict__ b,
    float* __restrict__ eff, int n)
{
    extern __shared__ char smem[];
    float*    s_bias = (float*)   (smem + P2_OFF_BIAS);
    uint32_t* Bs     = (uint32_t*)(smem + P2_OFF_B);   // transposed [128][128]
    const uint32_t sb = smem_u32(smem);
    const uint32_t a0b = sb + P2_OFF_A0;
    const uint32_t a1b = sb + P2_OFF_A1;
    const uint32_t btb = sb + P2_OFF_B;

    const int tid = threadIdx.x;
    const int wid = tid >> 5;
    const int lane = tid & 31;
    const int grp = lane >> 2;
    const int tg  = lane & 3;
    const int wm  = wid & 3;
    const int wn  = wid >> 2;
    const int l8  = lane & 7;
    const int lj1 = (lane >> 3) & 1;
    const int lj2 = lane >> 4;
    const int bxor = l8 << 2;

    for (int idx = tid; idx < 128 * 128; idx += 256) {
        int k = idx >> 7, nn = idx & 127;
        Bs[WTS(nn, k, 128)] = cvt_tf32(w2half[k * NF + nn]);
    }
    if (tid < 128) s_bias[tid] = b[tid];
    __syncthreads();

    const int ntiles = (n + 127) >> 7;
    const int r_st   = tid >> 1;
    const int half   = tid & 1;

    for (int tile = blockIdx.x; tile < ntiles; tile += gridDim.x) {
        const int n0 = tile << 7;
        const int row = n0 + r_st;
        const bool rv = (row < n);
        const size_t rowc = (size_t)(rv ? row : 0);

        {
            const float* src = agg + rowc * NF + half * 16;
#pragma unroll
            for (int q = 0; q < 4; q++)
                cp_async16(a0b + 4 * ACSW(r_st, half * 16 + q * 4), src + q * 4, rv);
            CP_COMMIT();
        }

        float acc[2][8][4];
#pragma unroll
        for (int mt = 0; mt < 2; mt++)
#pragma unroll
            for (int nt = 0; nt < 8; nt++)
#pragma unroll
                for (int i = 0; i < 4; i++) acc[mt][nt][i] = 0.f;

#pragma unroll 1
        for (int c = 0; c < 4; c++) {
            CP_WAIT0();
            __syncthreads();

            if (c + 1 < 4) {
                int cn = c + 1;
                const float* src = agg + rowc * NF + cn * 32;
                uint32_t abase = (cn & 1) ? a1b : a0b;
#pragma unroll
                for (int q = 0; q < 4; q++)
                    cp_async16(abase + 4 * ACSW(r_st, half * 16 + q * 4),
                               src + half * 16 + q * 4, rv);
                CP_COMMIT();
            }

            const uint32_t abufb = (c & 1) ? a1b : a0b;
#pragma unroll
            for (int s = 0; s < 4; s++) {
                const int ac = s * 8;
                const int kk = c * 32 + ac;
                const int bk = (kk + lj1 * 4) ^ bxor;
                uint32_t bf[8][2];
#pragma unroll
                for (int nt = 0; nt < 8; nt++) {
                    int nrow = wn * 64 + nt * 8 + l8;
                    ldsm_x2(bf[nt], btb + 4 * (nrow * 128 + bk));
                }
#pragma unroll
                for (int mt = 0; mt < 2; mt++) {
                    int arow = wm * 32 + mt * 16 + l8 + lj1 * 8;
                    int acol = (ac + lj2 * 4) ^ ((arow & 7) << 2);
                    uint32_t af[4];
                    ldsm_x4(af, abufb + 4 * (arow * 32 + acol));
#pragma unroll
                    for (int nt = 0; nt < 8; nt++)
                        mma_tf32(acc[mt][nt], af, bf[nt]);
                }
            }
        }

        // epilogue: eff = tf32(relu(acc + pe2 + b))
#pragma unroll
        for (int mt = 0; mt < 2; mt++) {
            int r_lo = wm * 32 + mt * 16 + grp;
            int r_hi = r_lo + 8;
            bool v_lo = (n0 + r_lo) < n;
            bool v_hi = (n0 + r_hi) < n;
#pragma unroll
            for (int nt = 0; nt < 8; nt++) {
                int col = wn * 64 + nt * 8 + tg * 2;
                float b0 = s_bias[col], b1 = s_bias[col + 1];
                if (v_lo) {
                    float2 p = *(const float2*)(pe2 + (size_t)(n0 + r_lo) * NF + col);
                    float2 v = { cvt_tf32f(fmaxf(acc[mt][nt][0] + p.x + b0, 0.f)),
                                 cvt_tf32f(fmaxf(acc[mt][nt][1] + p.y + b1, 0.f)) };
                    *(float2*)(eff + (size_t)(n0 + r_lo) * NF + col) = v;
                }
                if (v_hi) {
                    float2 p = *(const float2*)(pe2 + (size_t)(n0 + r_hi) * NF + col);
                    float2 v = { cvt_tf32f(fmaxf(acc[mt][nt][2] + p.x + b0, 0.f)),
                                 cvt_tf32f(fmaxf(acc[mt][nt][3] + p.y + b1, 0.f)) };
                    *(float2*)(eff + (size_t)(n0 + r_hi) * NF + col) = v;
                }
            }
        }
        __syncthreads();
    }
}

// ---------------------------------------------------------------------------
// Decoder (round-15/16 passing) — ldmatrix loads, W1/W2 transposed
// ---------------------------------------------------------------------------
#define DE_OFF_B1   0
#define DE_OFF_B2   512
#define DE_OFF_B3   1024
#define DE_OFF_W3   1088
#define DE_OFF_W1   2624
#define DE_OFF_W2   (DE_OFF_W1 + 65536)
#define DE_OFF_ACT  (DE_OFF_W2 + 65536)
#define DE_SMEM_BYTES (DE_OFF_ACT + 65536)

__global__ __launch_bounds__(256, 1) void k_decoder_mma(
    const float* __restrict__ eff,
    const float* __restrict__ w1, const float* __restrict__ b1,
    const float* __restrict__ w2, const float* __restrict__ b2,
    const float* __restrict__ w3, const float* __restrict__ b3,
    float* __restrict__ out, int n)
{
    extern __shared__ char smem[];
    float*    s_b1 = (float*)   (smem + DE_OFF_B1);
    float*    s_b2 = (float*)   (smem + DE_OFF_B2);
    float*    s_b3 = (float*)   (smem + DE_OFF_B3);
    float*    s_w3 = (float*)   (smem + DE_OFF_W3);
    uint32_t* W1s  = (uint32_t*)(smem + DE_OFF_W1);
    uint32_t* W2s  = (uint32_t*)(smem + DE_OFF_W2);
    uint32_t* As   = (uint32_t*)(smem + DE_OFF_ACT);
    const uint32_t sb = smem_u32(smem);
    const uint32_t actb = sb + DE_OFF_ACT;
    const uint32_t w1b  = sb + DE_OFF_W1;
    const uint32_t w2b  = sb + DE_OFF_W2;

    const int tid = threadIdx.x;
    const int wid = tid >> 5;
    const int lane = tid & 31;
    const int grp = lane >> 2;
    const int tg  = lane & 3;
    const int wm  = wid & 3;
    const int wn  = wid >> 2;
    const int l8  = lane & 7;
    const int lj1 = (lane >> 3) & 1;
    const int lj2 = lane >> 4;

    for (int idx = tid; idx < 128 * 128; idx += 256) {
        int k = idx >> 7, nn = idx & 127;
        W1s[WTS(nn, k, 128)] = cvt_tf32(w1[k * NF + nn]);
        W2s[WTS(nn, k, 128)] = cvt_tf32(w2[k * NF + nn]);
    }
    for (int idx = tid; idx < 384; idx += 256) s_w3[idx] = w3[idx];
    if (tid < 128) { s_b1[tid] = b1[tid]; s_b2[tid] = b2[tid]; }
    if (tid < 3)   s_b3[tid] = b3[tid];
    __syncthreads();

    const int ntiles = (n + 127) >> 7;
    const int r_st   = tid >> 1;
    const int half   = tid & 1;

    float acc[2][8][4];

    for (int tile = blockIdx.x; tile < ntiles; tile += gridDim.x) {
        const int n0 = tile << 7;
        const int row = n0 + r_st;
        const bool rv = (row < n);

        {
            const float* src = eff + (size_t)(rv ? row : 0) * NF + half * 64;
#pragma unroll
            for (int q = 0; q < 16; q++)
                cp_async16(actb + 4 * ASW(r_st, half * 64 + q * 4), src + q * 4, rv);
            CP_COMMIT();
            CP_WAIT0();
        }
        __syncthreads();

        // layer 1 (W1 transposed)
#pragma unroll
        for (int mt = 0; mt < 2; mt++)
#pragma unroll
            for (int nt = 0; nt < 8; nt++)
#pragma unroll
                for (int i = 0; i < 4; i++) acc[mt][nt][i] = 0.f;
#pragma unroll
        for (int s = 0; s < 16; s++) {
            const int kk = s * 8;
            const int bk = (kk + lj1 * 4) ^ (l8 << 2);
            uint32_t bf[8][2];
#pragma unroll
            for (int nt = 0; nt < 8; nt++) {
                int nrow = wn * 64 + nt * 8 + l8;
                ldsm_x2(bf[nt], w1b + 4 * (nrow * 128 + bk));
            }
#pragma unroll
            for (int mt = 0; mt < 2; mt++) {
                int arow = wm * 32 + mt * 16 + l8 + lj1 * 8;
                int acol = (kk + lj2 * 4) ^ ((arow & 7) << 2);
                uint32_t af[4];
                ldsm_x4(af, actb + 4 * (arow * 128 + acol));
#pragma unroll
                for (int nt = 0; nt < 8; nt++)
                    mma_tf32(acc[mt][nt], af, bf[nt]);
            }
        }
        __syncthreads();

#pragma unroll
        for (int mt = 0; mt < 2; mt++) {
            int r_lo = wm * 32 + mt * 16 + grp;
            int r_hi = r_lo + 8;
#pragma unroll
            for (int nt = 0; nt < 8; nt++) {
                int col = wn * 64 + nt * 8 + tg * 2;
                float b0 = s_b1[col], b1v = s_b1[col + 1];
                uint2 lo = { cvt_tf32(fmaxf(acc[mt][nt][0] + b0, 0.f)),
                             cvt_tf32(fmaxf(acc[mt][nt][1] + b1v, 0.f)) };
                uint2 hi = { cvt_tf32(fmaxf(acc[mt][nt][2] + b0, 0.f)),
                             cvt_tf32(fmaxf(acc[mt][nt][3] + b1v, 0.f)) };
                *(uint2*)(As + ASW(r_lo, col)) = lo;
                *(uint2*)(As + ASW(r_hi, col)) = hi;
            }
        }
        __syncthreads();

        // layer 2 (W2 transposed)
#pragma unroll
        for (int mt = 0; mt < 2; mt++)
#pragma unroll
            for (int nt = 0; nt < 8; nt++)
#pragma unroll
                for (int i = 0; i < 4; i++) acc[mt][nt][i] = 0.f;
#pragma unroll
        for (int s = 0; s < 16; s++) {
            const int kk = s * 8;
            const int bk = (kk + lj1 * 4) ^ (l8 << 2);
            uint32_t bf[8][2];
#pragma unroll
            for (int nt = 0; nt < 8; nt++) {
                int nrow = wn * 64 + nt * 8 + l8;
                ldsm_x2(bf[nt], w2b + 4 * (nrow * 128 + bk));
            }
#pragma unroll
            for (int mt = 0; mt < 2; mt++) {
                int arow = wm * 32 + mt * 16 + l8 + lj1 * 8;
                int acol = (kk + lj2 * 4) ^ ((arow & 7) << 2);
                uint32_t af[4];
                ldsm_x4(af, actb + 4 * (arow * 128 + acol));
#pragma unroll
                for (int nt = 0; nt < 8; nt++)
                    mma_tf32(acc[mt][nt], af, bf[nt]);
            }
        }
        __syncthreads();

#pragma unroll
        for (int mt = 0; mt < 2; mt++) {
            int r_lo = wm * 32 + mt * 16 + grp;
            int r_hi = r_lo + 8;
#pragma unroll
            for (int nt = 0; nt < 8; nt++) {
                int col = wn * 64 + nt * 8 + tg * 2;
                float b0 = s_b2[col], b1v = s_b2[col + 1];
                uint2 lo = { __float_as_uint(fmaxf(acc[mt][nt][0] + b0, 0.f)),
                             __float_as_uint(fmaxf(acc[mt][nt][1] + b1v, 0.f)) };
                uint2 hi = { __float_as_uint(fmaxf(acc[mt][nt][2] + b0, 0.f)),
                             __float_as_uint(fmaxf(acc[mt][nt][3] + b1v, 0.f)) };
                *(uint2*)(As + ASW(r_lo, col)) = lo;
                *(uint2*)(As + ASW(r_hi, col)) = hi;
            }
        }
        __syncthreads();

        for (int d = tid; d < 128 * 3; d += 256) {
            int r = d / 3, j = d % 3;
            if (n0 + r < n) {
                float a = s_b3[j];
#pragma unroll 4
                for (int k = 0; k < NF; k++)
                    a = fmaf(__uint_as_float(As[ASW(r, k)]), s_w3[k * 3 + j], a);
                out[(size_t)(n0 + r) * 3 + j] = a;
            }
        }
        __syncthreads();
    }
}

// ---------------------------------------------------------------------------
// launch
// ---------------------------------------------------------------------------
extern "C" void kernel_launch(void* const* d_in, const int* in_sizes, int n_in,
                              void* d_out, int out_size)
{
    const float* attr  = (const float*)d_in[0];
    const float* state = (const float*)d_in[1];
    const float* Ra    = (const float*)d_in[2];
    const int*   recv  = (const int*)  d_in[3];
    const int*   send  = (const int*)  d_in[4];
    // d_in[5] = pstep (fixed 2)
    const float* pe_w1 = (const float*)d_in[6];
    const float* pe_b1 = (const float*)d_in[7];
    const float* pe_w2 = (const float*)d_in[8];
    const float* pe_b2 = (const float*)d_in[9];
    const float* ee_w1 = (const float*)d_in[10];
    const float* ee_b1 = (const float*)d_in[11];
    const float* ee_w2 = (const float*)d_in[12];
    const float* ee_b2 = (const float*)d_in[13];
    const float* ee_w3 = (const float*)d_in[14];
    const float* ee_b3 = (const float*)d_in[15];
    const float* rp_w  = (const float*)d_in[16];
    const float* rp_b  = (const float*)d_in[17];
    const float* pp_w  = (const float*)d_in[18];
    const float* pp_b  = (const float*)d_in[19];
    const float* de_w1 = (const float*)d_in[20];
    const float* de_b1 = (const float*)d_in[21];
    const float* de_w2 = (const float*)d_in[22];
    const float* de_b2 = (const float*)d_in[23];
    const float* de_w3 = (const float*)d_in[24];
    const float* de_b3 = (const float*)d_in[25];

    const int n = in_sizes[0] / ATTR_W;   // 100000
    const int e = in_sizes[2] / REL_W;    // 500000

    float *pe, *pe2, *ee, *eff, *agg, *attr_r, *state_r, *ra_r;
    cudaGetSymbolAddress((void**)&pe,      g_pe);
    cudaGetSymbolAddress((void**)&pe2,     g_pe2);
    cudaGetSymbolAddress((void**)&ee,      g_ee);
    cudaGetSymbolAddress((void**)&eff,     g_eff);
    cudaGetSymbolAddress((void**)&agg,     g_agg);
    cudaGetSymbolAddress((void**)&attr_r,  g_attr_r);
    cudaGetSymbolAddress((void**)&state_r, g_state_r);
    cudaGetSymbolAddress((void**)&ra_r,    g_ra_r);

    cudaFuncSetAttribute(k_rel_prop_mma,
                         cudaFuncAttributeMaxDynamicSharedMemorySize, RP2_SMEM_BYTES);
    cudaFuncSetAttribute(k_rel_prop_mma4,
                         cudaFuncAttributeMaxDynamicSharedMemorySize, RP4_SMEM_BYTES);
    cudaFuncSetAttribute(k_edge_enc_mma,
                         cudaFuncAttributeMaxDynamicSharedMemorySize, EE_SMEM_BYTES);
    cudaFuncSetAttribute(k_pe2_mma,
                         cudaFuncAttributeMaxDynamicSharedMemorySize, P2_SMEM_BYTES);
    cudaFuncSetAttribute(k_part_prop2_mma,
                         cudaFuncAttributeMaxDynamicSharedMemorySize, P2_SMEM_BYTES);
    cudaFuncSetAttribute(k_decoder_mma,
                         cudaFuncAttributeMaxDynamicSharedMemorySize, DE_SMEM_BYTES);
    cudaFuncSetAttribute(k_node_enc_mma,
                         cudaFuncAttributeMaxDynamicSharedMemorySize, NE_SMEM_BYTES);

    // pre-round inputs once (rna) so edge_enc's cp.async gather is exact
    k_round3<<<1024, 256>>>(attr, attr_r, n * ATTR_W,
                            state, state_r, n * STATE_W,
                            Ra, ra_r, e * REL_W);

    // encoders + pe2 precompute (pe is constant across both propagation steps)
    k_node_enc_mma<<<148, 256, NE_SMEM_BYTES>>>(attr, state, pe_w1, pe_b1, pe_w2, pe_b2, pe, n);
    k_pe2_mma<<<296, 256, P2_SMEM_BYTES>>>(pe, pp_w, pe2, n);
    k_edge_enc_mma<<<148, 256, EE_SMEM_BYTES>>>(attr_r, state_r, ra_r, recv, send,
                                                ee_w1, ee_b1, ee_w2, ee_b2, ee_w3, ee_b3, ee, e);

    // propagation step 0: effect == 0 -> K=128 rel_prop, K=128 part_prop
    k_zero<<<1024, 256>>>((float4*)agg, n * NF / 4);
    k_rel_prop_mma4<<<296, 256, RP4_SMEM_BYTES>>>(ee, recv, rp_w, rp_b, agg, e);
    k_part_prop2_mma<<<296, 256, P2_SMEM_BYTES>>>(agg, pe2, pp_w + 128 * NF, pp_b, eff, n);

    // propagation step 1: full K=384 rel_prop, K=128 part_prop
    k_zero<<<1024, 256>>>((float4*)agg, n * NF / 4);
    k_rel_prop_mma<<<148, 256, RP2_SMEM_BYTES>>>(ee, eff, recv, send, rp_w, rp_b, agg, e);
    k_part_prop2_mma<<<296, 256, P2_SMEM_BYTES>>>(agg, pe2, pp_w + 128 * NF, pp_b, eff, n);

    // decoder
    k_decoder_mma<<<148, 256, DE_SMEM_BYTES>>>(eff, de_w1, de_b1, de_w2, de_b2,
                                               de_w3, de_b3, (float*)d_out, n);
}